// round 6
// baseline (speedup 1.0000x reference)
#include <cuda_runtime.h>
#include <cuda_bf16.h>
#include <math.h>
#include <stdint.h>

// Problem constants
#define B_    8
#define S_    512
#define H_    4096
#define HQ_   32
#define HKV_  8
#define D_    128
#define L_    1536
#define T_    2048
#define NT_   (B_*S_)
#define THETA_ 500000.0f
#define NQKV  (H_ + 2*HKV_*D_)      // 6144 combined output cols

// ---------------- scratch (device globals) ----------------------------------
__device__ float g_q   [(size_t)NT_*HQ_ *D_];
__device__ float g_ktmp[(size_t)NT_*HKV_*D_];
__device__ float g_vtmp[(size_t)NT_*HKV_*D_];

__device__ __nv_bfloat16 g_hid_h [(size_t)NT_*H_];
__device__ __nv_bfloat16 g_hid_l [(size_t)NT_*H_];
__device__ __nv_bfloat16 g_wqkvT_h[(size_t)NQKV*H_];   // rows: 0..4095 Q, 4096..5119 K, 5120..6143 V
__device__ __nv_bfloat16 g_wqkvT_l[(size_t)NQKV*H_];
__device__ __nv_bfloat16 g_woT_h [(size_t)H_*H_];
__device__ __nv_bfloat16 g_woT_l [(size_t)H_*H_];
__device__ __nv_bfloat16 g_attb_h[(size_t)NT_*H_];
__device__ __nv_bfloat16 g_attb_l[(size_t)NT_*H_];

__device__ __nv_bfloat16 g_qb_h[(size_t)NT_*HQ_*D_];
__device__ __nv_bfloat16 g_qb_l[(size_t)NT_*HQ_*D_];
__device__ __nv_bfloat16 g_kb_h[(size_t)B_*T_*HKV_*D_];
__device__ __nv_bfloat16 g_kb_l[(size_t)B_*T_*HKV_*D_];
__device__ __nv_bfloat16 g_vb_h[(size_t)B_*T_*HKV_*D_];
__device__ __nv_bfloat16 g_vb_l[(size_t)B_*T_*HKV_*D_];

// ---------------- helpers ----------------------------------------------------
__device__ __forceinline__ uint32_t smem_u32(const void* p) {
    uint32_t r;
    asm("{ .reg .u64 t; cvta.to.shared.u64 t, %1; cvt.u32.u64 %0, t; }"
        : "=r"(r) : "l"(p));
    return r;
}
__device__ __forceinline__ uint16_t bf_hi(float x) {
    __nv_bfloat16 b = __float2bfloat16(x);
    return *reinterpret_cast<uint16_t*>(&b);
}
__device__ __forceinline__ float bf_back(uint16_t u) {
    __nv_bfloat16 b = *reinterpret_cast<__nv_bfloat16*>(&u);
    return __bfloat162float(b);
}
__device__ __forceinline__ uint32_t pack_bf2(float lo, float hi) {
    uint32_t r;
    asm("cvt.rn.bf16x2.f32 %0, %1, %2;" : "=r"(r) : "f"(hi), "f"(lo));
    return r;
}
__device__ __forceinline__ float bf2lo(uint32_t p) { return __uint_as_float(p << 16); }
__device__ __forceinline__ float bf2hi(uint32_t p) { return __uint_as_float(p & 0xFFFF0000u); }

#define CP_ASYNC16(dst, src) \
    asm volatile("cp.async.cg.shared.global [%0], [%1], 16;" :: "r"(dst), "l"(src))
#define CP_COMMIT() asm volatile("cp.async.commit_group;")
#define CP_WAIT2()  asm volatile("cp.async.wait_group 2;")
#define CP_WAIT1()  asm volatile("cp.async.wait_group 1;")
#define CP_WAIT0()  asm volatile("cp.async.wait_group 0;")

#define LDSM4(r, a) \
    asm volatile("ldmatrix.sync.aligned.m8n8.x4.shared.b16 {%0,%1,%2,%3}, [%4];" \
                 : "=r"((r)[0]), "=r"((r)[1]), "=r"((r)[2]), "=r"((r)[3]) : "r"(a))
#define LDSM4T(r, a) \
    asm volatile("ldmatrix.sync.aligned.m8n8.x4.trans.shared.b16 {%0,%1,%2,%3}, [%4];" \
                 : "=r"((r)[0]), "=r"((r)[1]), "=r"((r)[2]), "=r"((r)[3]) : "r"(a))
#define LDSM2(r, a) \
    asm volatile("ldmatrix.sync.aligned.m8n8.x2.shared.b16 {%0,%1}, [%2];" \
                 : "=r"((r)[0]), "=r"((r)[1]) : "r"(a))

#define MMA_BF16(c, a, b0v, b1v) \
    asm volatile("mma.sync.aligned.m16n8k16.row.col.f32.bf16.bf16.f32 " \
                 "{%0,%1,%2,%3}, {%4,%5,%6,%7}, {%8,%9}, {%0,%1,%2,%3};" \
                 : "+f"((c)[0]), "+f"((c)[1]), "+f"((c)[2]), "+f"((c)[3]) \
                 : "r"((a)[0]), "r"((a)[1]), "r"((a)[2]), "r"((a)[3]), \
                   "r"(b0v), "r"(b1v))

// ---------------- fp32 -> bf16 hi/lo split -----------------------------------
__global__ void conv_split(const float4* __restrict__ in,
                           uint2* __restrict__ oh, uint2* __restrict__ ol, int n4)
{
    int i = blockIdx.x * blockDim.x + threadIdx.x;
    if (i >= n4) return;
    float4 v = in[i];
    uint16_t hx = bf_hi(v.x), hy = bf_hi(v.y), hz = bf_hi(v.z), hw = bf_hi(v.w);
    uint16_t lx = bf_hi(v.x - bf_back(hx));
    uint16_t ly = bf_hi(v.y - bf_back(hy));
    uint16_t lz = bf_hi(v.z - bf_back(hz));
    uint16_t lw = bf_hi(v.w - bf_back(hw));
    oh[i] = make_uint2((uint32_t)hx | ((uint32_t)hy << 16),
                       (uint32_t)hz | ((uint32_t)hw << 16));
    ol[i] = make_uint2((uint32_t)lx | ((uint32_t)ly << 16),
                       (uint32_t)lz | ((uint32_t)lw << 16));
}

__global__ void conv_splitT(const float* __restrict__ in,
                            __nv_bfloat16* __restrict__ oh,
                            __nv_bfloat16* __restrict__ ol, int K, int N)
{
    __shared__ float t[32][33];
    const int n0 = blockIdx.x * 32;
    const int k0 = blockIdx.y * 32;
    const int x = threadIdx.x, y = threadIdx.y;
#pragma unroll
    for (int dy = 0; dy < 4; dy++)
        t[y + dy * 8][x] = in[(size_t)(k0 + y + dy * 8) * N + n0 + x];
    __syncthreads();
#pragma unroll
    for (int dy = 0; dy < 4; dy++) {
        int nrow = y + dy * 8;
        float v = t[x][nrow];
        uint16_t h = bf_hi(v);
        uint16_t l = bf_hi(v - bf_back(h));
        size_t o = (size_t)(n0 + nrow) * K + k0 + x;
        oh[o] = *reinterpret_cast<__nv_bfloat16*>(&h);
        ol[o] = *reinterpret_cast<__nv_bfloat16*>(&l);
    }
}

// ============================================================================
// bf16-split GEMM, 3-stage cp.async pipeline.
// C cols [0,n0) -> C0 (ld0); [n0,n1) -> C1 (ld1); [n1,..) -> C2 (ld2).
// ============================================================================
#define GEMM_SMEM (3 * 32768)

__global__ __launch_bounds__(256) void gemm_bf16(
    const __nv_bfloat16* __restrict__ Ah, const __nv_bfloat16* __restrict__ Al,
    const __nv_bfloat16* __restrict__ Bh, const __nv_bfloat16* __restrict__ Bl,
    float* __restrict__ C0, float* __restrict__ C1, float* __restrict__ C2,
    int n0, int n1, int ld0, int ld1, int ld2, int K)
{
    extern __shared__ char smem[];
    const uint32_t sb = smem_u32(smem);
    const int tid  = threadIdx.x;
    const int lane = tid & 31;
    const int wid  = tid >> 5;
    const int bm   = blockIdx.y * 128;
    const int bn   = blockIdx.x * 128;
    const int wm   = (wid >> 2) * 64;
    const int wn   = (wid & 3) * 32;

    const int lrow = tid >> 2;
    const int lchk = tid & 3;
    const uint32_t dsw = (uint32_t)(lrow * 64 + ((lchk ^ ((lrow >> 1) & 3)) * 16));

    const __nv_bfloat16* srcA[2] = {Ah, Al};
    const __nv_bfloat16* srcB[2] = {Bh, Bl};

    const int arow = ((lane >> 3) & 1) * 8 + (lane & 7);
    const int akc  = lane >> 4;
    const int aph  = ((lane & 7) >> 1) & 3;
    const int brow = lane & 7;
    const int bkc  = (lane >> 3) & 1;
    const int bph  = (brow >> 1) & 3;

    const uint32_t aBase = (uint32_t)((wm + arow) * 64);
    const uint32_t bBase = (uint32_t)((wn + brow) * 64);

    float acc[4][4][4];
#pragma unroll
    for (int i = 0; i < 4; i++)
#pragma unroll
        for (int j = 0; j < 4; j++) {
            acc[i][j][0] = 0.f; acc[i][j][1] = 0.f;
            acc[i][j][2] = 0.f; acc[i][j][3] = 0.f;
        }

    const int nk = K / 32;

    auto issue = [&](int st, int k0) {
        const uint32_t s = sb + st * 32768;
#pragma unroll
        for (int p = 0; p < 2; p++) {
            const __nv_bfloat16* g = srcA[p] + (size_t)(bm + lrow) * K + k0 + lchk * 8;
            uint32_t d = s + p * 8192 + dsw;
            CP_ASYNC16(d, g);
            CP_ASYNC16(d + 4096, g + (size_t)64 * K);
        }
#pragma unroll
        for (int p = 0; p < 2; p++) {
            const __nv_bfloat16* g = srcB[p] + (size_t)(bn + lrow) * K + k0 + lchk * 8;
            uint32_t d = s + 16384 + p * 8192 + dsw;
            CP_ASYNC16(d, g);
            CP_ASYNC16(d + 4096, g + (size_t)64 * K);
        }
        CP_COMMIT();
    };

    issue(0, 0);
    issue(1, 32);
    issue(2, 64);

    int st = 0;
    for (int ck = 0; ck < nk; ck++) {
        const int rem = nk - 1 - ck;
        if (rem >= 2) { CP_WAIT2(); } else if (rem == 1) { CP_WAIT1(); } else { CP_WAIT0(); }
        __syncthreads();

        const uint32_t s  = sb + st * 32768;
        const uint32_t sAh = s + aBase;
        const uint32_t sAl = s + 8192 + aBase;
        const uint32_t sBh = s + 16384 + bBase;
        const uint32_t sBl = s + 24576 + bBase;

#pragma unroll
        for (int ks = 0; ks < 2; ks++) {
            const uint32_t cA = (uint32_t)(((ks * 2 + akc) ^ aph) * 16);
            const uint32_t cB = (uint32_t)(((ks * 2 + bkc) ^ bph) * 16);

            uint32_t aF[4][4];
#pragma unroll
            for (int i = 0; i < 4; i++) LDSM4(aF[i], sAh + i * 1024 + cA);
            uint32_t bH[4][2], bL[4][2];
#pragma unroll
            for (int j = 0; j < 4; j++) LDSM2(bH[j], sBh + j * 512 + cB);
#pragma unroll
            for (int j = 0; j < 4; j++) LDSM2(bL[j], sBl + j * 512 + cB);

#pragma unroll
            for (int i = 0; i < 4; i++)
#pragma unroll
                for (int j = 0; j < 4; j++)
                    MMA_BF16(acc[i][j], aF[i], bH[j][0], bH[j][1]);
#pragma unroll
            for (int i = 0; i < 4; i++)
#pragma unroll
                for (int j = 0; j < 4; j++)
                    MMA_BF16(acc[i][j], aF[i], bL[j][0], bL[j][1]);

#pragma unroll
            for (int i = 0; i < 4; i++) LDSM4(aF[i], sAl + i * 1024 + cA);
#pragma unroll
            for (int i = 0; i < 4; i++)
#pragma unroll
                for (int j = 0; j < 4; j++)
                    MMA_BF16(acc[i][j], aF[i], bH[j][0], bH[j][1]);
        }
        __syncthreads();
        if (ck + 3 < nk) issue(st, (ck + 3) * 32);
        st = (st == 2) ? 0 : st + 1;
    }

    // epilogue: select output buffer by column block (tiles never straddle)
    float* Cp;
    int ld, cbase;
    if (bn < n0)      { Cp = C0; ld = ld0; cbase = bn; }
    else if (bn < n1) { Cp = C1; ld = ld1; cbase = bn - n0; }
    else              { Cp = C2; ld = ld2; cbase = bn - n1; }

    const int g4 = lane >> 2, t4 = lane & 3;
#pragma unroll
    for (int i = 0; i < 4; i++) {
        const int row = bm + wm + i * 16 + g4;
#pragma unroll
        for (int j = 0; j < 4; j++) {
            const int col = cbase + wn + j * 8 + t4 * 2;
            *reinterpret_cast<float2*>(&Cp[(size_t)row * ld + col]) =
                make_float2(acc[i][j][0], acc[i][j][1]);
            *reinterpret_cast<float2*>(&Cp[(size_t)(row + 8) * ld + col]) =
                make_float2(acc[i][j][2], acc[i][j][3]);
        }
    }
}

// ---------------- RoPE Q -> bf16 split ---------------------------------------
__global__ void rope_q_kernel()
{
    int idx = blockIdx.x * blockDim.x + threadIdx.x;
    if (idx >= NT_ * HQ_ * 64) return;
    int d   = idx & 63;
    int th  = idx >> 6;
    int tok = th >> 5;
    int s   = tok & (S_ - 1);
    float pos = (float)(L_ + s);
    float inv = powf(THETA_, -(float)d * (1.0f / 64.0f));
    float ang = pos * inv;
    float c = cosf(ang), sn = sinf(ang);
    const float* base = g_q + (size_t)th * D_;
    float x1 = base[d], x2 = base[d + 64];
    float y1 = x1 * c - x2 * sn;
    float y2 = x2 * c + x1 * sn;
    size_t o = (size_t)th * D_;
    uint16_t h1 = bf_hi(y1), h2 = bf_hi(y2);
    g_qb_h[o + d]      = *reinterpret_cast<__nv_bfloat16*>(&h1);
    g_qb_h[o + d + 64] = *reinterpret_cast<__nv_bfloat16*>(&h2);
    uint16_t l1 = bf_hi(y1 - bf_back(h1)), l2 = bf_hi(y2 - bf_back(h2));
    g_qb_l[o + d]      = *reinterpret_cast<__nv_bfloat16*>(&l1);
    g_qb_l[o + d + 64] = *reinterpret_cast<__nv_bfloat16*>(&l2);
}

__global__ void rope_scatter_k_kernel()
{
    int idx = blockIdx.x * blockDim.x + threadIdx.x;
    if (idx >= NT_ * HKV_ * 64) return;
    int d   = idx & 63;
    int th  = idx >> 6;
    int tok = th >> 3;
    int kvh = th & 7;
    int b   = tok >> 9;
    int s   = tok & 511;
    float pos = (float)(L_ + s);
    float inv = powf(THETA_, -(float)d * (1.0f / 64.0f));
    float ang = pos * inv;
    float c = cosf(ang), sn = sinf(ang);
    const float* src = g_ktmp + (size_t)th * D_;
    float x1 = src[d], x2 = src[d + 64];
    float y1 = x1 * c - x2 * sn;
    float y2 = x2 * c + x1 * sn;
    size_t o = (((size_t)(b * T_ + L_ + s)) * HKV_ + kvh) * D_;
    uint16_t h1 = bf_hi(y1), h2 = bf_hi(y2);
    g_kb_h[o + d]      = *reinterpret_cast<__nv_bfloat16*>(&h1);
    g_kb_h[o + d + 64] = *reinterpret_cast<__nv_bfloat16*>(&h2);
    uint16_t l1 = bf_hi(y1 - bf_back(h1)), l2 = bf_hi(y2 - bf_back(h2));
    g_kb_l[o + d]      = *reinterpret_cast<__nv_bfloat16*>(&l1);
    g_kb_l[o + d + 64] = *reinterpret_cast<__nv_bfloat16*>(&l2);
}

__global__ void scatter_v_kernel()
{
    int idx = blockIdx.x * blockDim.x + threadIdx.x;
    const int n = NT_ * HKV_ * D_ / 2;
    if (idx >= n) return;
    int e   = idx * 2;
    int tok = e >> 10;
    int r   = e & 1023;
    int b   = tok >> 9;
    int s   = tok & 511;
    float2 v = reinterpret_cast<const float2*>(g_vtmp)[idx];
    uint16_t hx = bf_hi(v.x), hy = bf_hi(v.y);
    uint16_t lx = bf_hi(v.x - bf_back(hx)), ly = bf_hi(v.y - bf_back(hy));
    size_t o2 = ((((size_t)(b * T_ + L_ + s)) * HKV_) * D_ + r) >> 1;
    reinterpret_cast<uint32_t*>(g_vb_h)[o2] = (uint32_t)hx | ((uint32_t)hy << 16);
    reinterpret_cast<uint32_t*>(g_vb_l)[o2] = (uint32_t)lx | ((uint32_t)ly << 16);
}

__global__ void copy_cache_kernel(const float2* __restrict__ kc,
                                  const float2* __restrict__ vc)
{
    int idx = blockIdx.x * blockDim.x + threadIdx.x;
    const int n = B_ * L_ * HKV_ * D_ / 2;
    if (idx >= n) return;
    const int perb = L_ * HKV_ * D_ / 2;
    int b = idx / perb;
    size_t o2 = (size_t)idx + (size_t)b * ((T_ - L_) * HKV_ * D_ / 2);
    float2 k = kc[idx];
    float2 v = vc[idx];
    uint16_t khx = bf_hi(k.x), khy = bf_hi(k.y);
    uint16_t klx = bf_hi(k.x - bf_back(khx)), kly = bf_hi(k.y - bf_back(khy));
    uint16_t vhx = bf_hi(v.x), vhy = bf_hi(v.y);
    uint16_t vlx = bf_hi(v.x - bf_back(vhx)), vly = bf_hi(v.y - bf_back(vhy));
    reinterpret_cast<uint32_t*>(g_kb_h)[o2] = (uint32_t)khx | ((uint32_t)khy << 16);
    reinterpret_cast<uint32_t*>(g_kb_l)[o2] = (uint32_t)klx | ((uint32_t)kly << 16);
    reinterpret_cast<uint32_t*>(g_vb_h)[o2] = (uint32_t)vhx | ((uint32_t)vhy << 16);
    reinterpret_cast<uint32_t*>(g_vb_l)[o2] = (uint32_t)vlx | ((uint32_t)vly << 16);
}

// ============================================================================
// Tensor-core flash attention (unchanged from R5)
// ============================================================================
#define AT_STAGE 65536
#define AT_SMEM  (2 * AT_STAGE)
#define SC_LOG2E 0.12751884817f

__global__ __launch_bounds__(256, 1) void attn_mma()
{
    extern __shared__ char smem[];
    const uint32_t sb = smem_u32(smem);
    const int tid  = threadIdx.x;
    const int lane = tid & 31;
    const int w    = tid >> 5;
    const int g    = lane >> 2;
    const int t4   = lane & 3;
    const int qt   = blockIdx.x;
    const int hq   = blockIdx.y;
    const int b    = blockIdx.z;
    const int kvh  = hq >> 2;

    {
        const int qr  = tid >> 1;
        const int qcb = (tid & 1) * 8;
        const size_t qo = ((size_t)(b * S_ + qt * 128 + qr)) * (HQ_ * D_) + hq * D_;
#pragma unroll
        for (int i = 0; i < 8; i++) {
            int ch = qcb + i;
            uint32_t d = sb + qr * 256 + ((ch ^ (qr & 7)) * 16);
            CP_ASYNC16(d,         g_qb_h + qo + ch * 8);
            CP_ASYNC16(d + 32768, g_qb_l + qo + ch * 8);
        }
        CP_COMMIT();
        CP_WAIT0();
    }
    __syncthreads();

    uint32_t qh[8][4], ql[8][4];
    {
        const int tt  = lane >> 3;
        const int qrow = 16 * w + (tt & 1) * 8 + (lane & 7);
        const int chi  = tt >> 1;
#pragma unroll
        for (int kk = 0; kk < 8; kk++) {
            uint32_t a = sb + qrow * 256 + (((2 * kk + chi) ^ (qrow & 7)) * 16);
            LDSM4(qh[kk], a);
            LDSM4(ql[kk], a + 32768);
        }
    }
    __syncthreads();

    const int ntiles = 26 + 2 * qt;
    const int mask_from = 24 + 2 * qt;

    auto issueKV = [&](int stage, int kt) {
        const uint32_t s = sb + stage * AT_STAGE;
        const int trow = tid >> 2;
        const int cb   = (tid & 3) * 4;
        const size_t go = (((size_t)(b * T_ + kt * 64 + trow)) * HKV_ + kvh) * D_;
        const uint32_t rb = s + trow * 256;
#pragma unroll
        for (int i = 0; i < 4; i++) {
            int ch = cb + i;
            uint32_t d = rb + ((ch ^ (trow & 7)) * 16);
            CP_ASYNC16(d,         g_kb_h + go + ch * 8);
            CP_ASYNC16(d + 16384, g_kb_l + go + ch * 8);
            CP_ASYNC16(d + 32768, g_vb_h + go + ch * 8);
            CP_ASYNC16(d + 49152, g_vb_l + go + ch * 8);
        }
        CP_COMMIT();
    };

    issueKV(0, 0);
    issueKV(1, 1);

    float oacc[16][4];
#pragma unroll
    for (int j = 0; j < 16; j++) {
        oacc[j][0] = 0.f; oacc[j][1] = 0.f; oacc[j][2] = 0.f; oacc[j][3] = 0.f;
    }
    float m0 = -1e30f, m1 = -1e30f, l0 = 0.f, l1 = 0.f;

    const int tt   = lane >> 3;
    const int krb  = (tt >> 1) * 8 + (lane & 7);
    const int kch1 = tt & 1;
    const int vrb  = (tt & 1) * 8 + (lane & 7);
    const int vch1 = tt >> 1;

    for (int kt = 0; kt < ntiles; kt++) {
        if (kt + 1 < ntiles) { CP_WAIT1(); } else { CP_WAIT0(); }
        __syncthreads();

        const uint32_t s = sb + (kt & 1) * AT_STAGE;

        float sacc[8][4];
#pragma unroll
        for (int j = 0; j < 8; j++) {
            sacc[j][0] = 0.f; sacc[j][1] = 0.f; sacc[j][2] = 0.f; sacc[j][3] = 0.f;
        }
#pragma unroll
        for (int kk = 0; kk < 8; kk++) {
#pragma unroll
            for (int jp = 0; jp < 4; jp++) {
                const int trow = jp * 16 + krb;
                const uint32_t addr = s + trow * 256 +
                                      (((2 * kk + kch1) ^ (trow & 7)) * 16);
                uint32_t bh[4], bl[4];
                LDSM4(bh, addr);
                LDSM4(bl, addr + 16384);
                MMA_BF16(sacc[2*jp],   qh[kk], bh[0], bh[1]);
                MMA_BF16(sacc[2*jp+1], qh[kk], bh[2], bh[3]);
                MMA_BF16(sacc[2*jp],   qh[kk], bl[0], bl[1]);
                MMA_BF16(sacc[2*jp+1], qh[kk], bl[2], bl[3]);
                MMA_BF16(sacc[2*jp],   ql[kk], bh[0], bh[1]);
                MMA_BF16(sacc[2*jp+1], ql[kk], bh[2], bh[3]);
            }
        }

        if (kt >= mask_from) {
            const int colb = kt * 64 + 2 * t4;
            const int alw0 = L_ + qt * 128 + 16 * w + g;
            const int alw1 = alw0 + 8;
#pragma unroll
            for (int j = 0; j < 8; j++) {
                int c0 = colb + j * 8;
                if (c0 > alw0)     sacc[j][0] = -1e30f;
                if (c0 + 1 > alw0) sacc[j][1] = -1e30f;
                if (c0 > alw1)     sacc[j][2] = -1e30f;
                if (c0 + 1 > alw1) sacc[j][3] = -1e30f;
            }
        }

        float rm0 = -1e30f, rm1 = -1e30f;
#pragma unroll
        for (int j = 0; j < 8; j++) {
            rm0 = fmaxf(rm0, fmaxf(sacc[j][0], sacc[j][1]));
            rm1 = fmaxf(rm1, fmaxf(sacc[j][2], sacc[j][3]));
        }
        rm0 = fmaxf(rm0, __shfl_xor_sync(0xFFFFFFFFu, rm0, 1));
        rm0 = fmaxf(rm0, __shfl_xor_sync(0xFFFFFFFFu, rm0, 2));
        rm1 = fmaxf(rm1, __shfl_xor_sync(0xFFFFFFFFu, rm1, 1));
        rm1 = fmaxf(rm1, __shfl_xor_sync(0xFFFFFFFFu, rm1, 2));

        const float nm0 = fmaxf(m0, rm0), nm1 = fmaxf(m1, rm1);
        const float f0 = exp2f((m0 - nm0) * SC_LOG2E);
        const float f1 = exp2f((m1 - nm1) * SC_LOG2E);
        float rs0 = 0.f, rs1 = 0.f;
#pragma unroll
        for (int j = 0; j < 8; j++) {
            sacc[j][0] = exp2f((sacc[j][0] - nm0) * SC_LOG2E);
            sacc[j][1] = exp2f((sacc[j][1] - nm0) * SC_LOG2E);
            sacc[j][2] = exp2f((sacc[j][2] - nm1) * SC_LOG2E);
            sacc[j][3] = exp2f((sacc[j][3] - nm1) * SC_LOG2E);
            rs0 += sacc[j][0] + sacc[j][1];
            rs1 += sacc[j][2] + sacc[j][3];
        }
        rs0 += __shfl_xor_sync(0xFFFFFFFFu, rs0, 1);
        rs0 += __shfl_xor_sync(0xFFFFFFFFu, rs0, 2);
        rs1 += __shfl_xor_sync(0xFFFFFFFFu, rs1, 1);
        rs1 += __shfl_xor_sync(0xFFFFFFFFu, rs1, 2);
        l0 = l0 * f0 + rs0;
        l1 = l1 * f1 + rs1;
        m0 = nm0; m1 = nm1;

#pragma unroll
        for (int j = 0; j < 16; j++) {
            oacc[j][0] *= f0; oacc[j][1] *= f0;
            oacc[j][2] *= f1; oacc[j][3] *= f1;
        }

        uint32_t ph[4][4], pl[4][4];
#pragma unroll
        for (int kc = 0; kc < 4; kc++) {
            float v00 = sacc[2*kc][0],   v01 = sacc[2*kc][1];
            float v02 = sacc[2*kc][2],   v03 = sacc[2*kc][3];
            float v10 = sacc[2*kc+1][0], v11 = sacc[2*kc+1][1];
            float v12 = sacc[2*kc+1][2], v13 = sacc[2*kc+1][3];
            ph[kc][0] = pack_bf2(v00, v01);
            ph[kc][1] = pack_bf2(v02, v03);
            ph[kc][2] = pack_bf2(v10, v11);
            ph[kc][3] = pack_bf2(v12, v13);
            pl[kc][0] = pack_bf2(v00 - bf2lo(ph[kc][0]), v01 - bf2hi(ph[kc][0]));
            pl[kc][1] = pack_bf2(v02 - bf2lo(ph[kc][1]), v03 - bf2hi(ph[kc][1]));
            pl[kc][2] = pack_bf2(v10 - bf2lo(ph[kc][2]), v11 - bf2hi(ph[kc][2]));
            pl[kc][3] = pack_bf2(v12 - bf2lo(ph[kc][3]), v13 - bf2hi(ph[kc][3]));
        }

        const uint32_t vbase = s + 32768;
#pragma unroll
        for (int jp2 = 0; jp2 < 8; jp2++) {
#pragma unroll
            for (int kc = 0; kc < 4; kc++) {
                const int trow = kc * 16 + vrb;
                const uint32_t addr = vbase + trow * 256 +
                                      (((jp2 * 2 + vch1) ^ (trow & 7)) * 16);
                uint32_t vh[4], vl[4];
                LDSM4T(vh, addr);
                LDSM4T(vl, addr + 16384);
                MMA_BF16(oacc[2*jp2],   ph[kc], vh[0], vh[1]);
                MMA_BF16(oacc[2*jp2+1], ph[kc], vh[2], vh[3]);
                MMA_BF16(oacc[2*jp2],   ph[kc], vl[0], vl[1]);
                MMA_BF16(oacc[2*jp2+1], ph[kc], vl[2], vl[3]);
                MMA_BF16(oacc[2*jp2],   pl[kc], vh[0], vh[1]);
                MMA_BF16(oacc[2*jp2+1], pl[kc], vh[2], vh[3]);
            }
        }

        __syncthreads();
        if (kt + 2 < ntiles) issueKV(kt & 1, kt + 2);
    }

    const float il0 = 1.0f / l0;
    const float il1 = 1.0f / l1;
    const size_t tok0 = (size_t)(b * S_ + qt * 128 + 16 * w + g);
    uint32_t* oh32 = reinterpret_cast<uint32_t*>(g_attb_h);
    uint32_t* ol32 = reinterpret_cast<uint32_t*>(g_attb_l);
#pragma unroll
    for (int jn = 0; jn < 16; jn++) {
        float o0 = oacc[jn][0] * il0, o1 = oacc[jn][1] * il0;
        float o2 = oacc[jn][2] * il1, o3 = oacc[jn][3] * il1;
        const size_t a0 = (tok0 * (HQ_ * D_) + hq * D_ + jn * 8 + 2 * t4) >> 1;
        const size_t a1 = a0 + (8 * (HQ_ * D_) >> 1);
        uint32_t h01 = pack_bf2(o0, o1);
        uint32_t h23 = pack_bf2(o2, o3);
        oh32[a0] = h01;
        oh32[a1] = h23;
        ol32[a0] = pack_bf2(o0 - bf2lo(h01), o1 - bf2hi(h01));
        ol32[a1] = pack_bf2(o2 - bf2lo(h23), o3 - bf2hi(h23));
    }
}

// ---------------- launcher ---------------------------------------------------
extern "C" void kernel_launch(void* const* d_in, const int* in_sizes, int n_in,
                              void* d_out, int out_size)
{
    const float* hidden  = (const float*)d_in[0];
    const float* k_cache = (const float*)d_in[1];
    const float* v_cache = (const float*)d_in[2];
    const float* wq      = (const float*)d_in[3];
    const float* wk      = (const float*)d_in[4];
    const float* wv      = (const float*)d_in[5];
    const float* wo      = (const float*)d_in[6];
    float* out = (float*)d_out;

    float *q, *ktmp, *vtmp;
    cudaGetSymbolAddress((void**)&q,    g_q);
    cudaGetSymbolAddress((void**)&ktmp, g_ktmp);
    cudaGetSymbolAddress((void**)&vtmp, g_vtmp);

    __nv_bfloat16 *hid_h, *hid_l, *wqkv_h, *wqkv_l, *wo_h, *wo_l, *attb_h, *attb_l;
    cudaGetSymbolAddress((void**)&hid_h,  g_hid_h);
    cudaGetSymbolAddress((void**)&hid_l,  g_hid_l);
    cudaGetSymbolAddress((void**)&wqkv_h, g_wqkvT_h);
    cudaGetSymbolAddress((void**)&wqkv_l, g_wqkvT_l);
    cudaGetSymbolAddress((void**)&wo_h,   g_woT_h);
    cudaGetSymbolAddress((void**)&wo_l,   g_woT_l);
    cudaGetSymbolAddress((void**)&attb_h, g_attb_h);
    cudaGetSymbolAddress((void**)&attb_l, g_attb_l);

    cudaFuncSetAttribute(gemm_bf16,
                         cudaFuncAttributeMaxDynamicSharedMemorySize, GEMM_SMEM);
    cudaFuncSetAttribute(attn_mma,
                         cudaFuncAttributeMaxDynamicSharedMemorySize, AT_SMEM);

    // conversions (QKV weights concatenated transposed: rows 0..4095=Q, +1024=K, +1024=V)
    conv_split<<<(NT_ * H_ / 4 + 255) / 256, 256>>>(
        (const float4*)hidden, (uint2*)hid_h, (uint2*)hid_l, NT_ * H_ / 4);
    conv_splitT<<<dim3(H_ / 32, H_ / 32), dim3(32, 8)>>>(wq, wqkv_h, wqkv_l, H_, H_);
    conv_splitT<<<dim3((HKV_ * D_) / 32, H_ / 32), dim3(32, 8)>>>(
        wk, wqkv_h + (size_t)H_ * H_, wqkv_l + (size_t)H_ * H_, H_, HKV_ * D_);
    conv_splitT<<<dim3((HKV_ * D_) / 32, H_ / 32), dim3(32, 8)>>>(
        wv, wqkv_h + (size_t)(H_ + HKV_ * D_) * H_, wqkv_l + (size_t)(H_ + HKV_ * D_) * H_,
        H_, HKV_ * D_);
    conv_splitT<<<dim3(H_ / 32, H_ / 32), dim3(32, 8)>>>(wo, wo_h, wo_l, H_, H_);

    // fused QKV projection: C cols [0,4096)->q, [4096,5120)->ktmp, [5120,6144)->vtmp
    gemm_bf16<<<dim3(NQKV / 128, NT_ / 128), 256, GEMM_SMEM>>>(
        hid_h, hid_l, wqkv_h, wqkv_l,
        q, ktmp, vtmp, H_, H_ + HKV_ * D_, H_, HKV_ * D_, HKV_ * D_, H_);

    // rope + KV assembly
    rope_q_kernel<<<(NT_ * HQ_ * 64) / 256, 256>>>();
    rope_scatter_k_kernel<<<(NT_ * HKV_ * 64) / 256, 256>>>();
    scatter_v_kernel<<<(NT_ * HKV_ * D_ / 2) / 256, 256>>>();
    copy_cache_kernel<<<(B_ * L_ * HKV_ * D_ / 2) / 256, 256>>>(
        (const float2*)k_cache, (const float2*)v_cache);

    // attention
    attn_mma<<<dim3(S_ / 128, HQ_, B_), 256, AT_SMEM>>>();

    // output projection (single target buffer)
    gemm_bf16<<<dim3(H_ / 128, NT_ / 128), 256, GEMM_SMEM>>>(
        attb_h, attb_l, wo_h, wo_l,
        out, out, out, H_, H_, H_, H_, H_, H_);
}

// round 7
// speedup vs baseline: 1.2980x; 1.2980x over previous
#include <cuda_runtime.h>
#include <cuda_fp16.h>
#include <math.h>
#include <stdint.h>

// Problem constants
#define B_    8
#define S_    512
#define H_    4096
#define HQ_   32
#define HKV_  8
#define D_    128
#define L_    1536
#define T_    2048
#define NT_   (B_*S_)
#define THETA_ 500000.0f
#define NQKV  (H_ + 2*HKV_*D_)      // 6144

// ---------------- scratch (device globals) ----------------------------------
__device__ float g_q   [(size_t)NT_*HQ_ *D_];
__device__ float g_ktmp[(size_t)NT_*HKV_*D_];
__device__ float g_vtmp[(size_t)NT_*HKV_*D_];

__device__ __half g_hid_h [(size_t)NT_*H_];
__device__ __half g_wqkvT_h[(size_t)NQKV*H_];
__device__ __half g_wqkvT_l[(size_t)NQKV*H_];
__device__ __half g_woT_h [(size_t)H_*H_];
__device__ __half g_woT_l [(size_t)H_*H_];
__device__ __half g_attb_h[(size_t)NT_*H_];

__device__ __half g_qb_h[(size_t)NT_*HQ_*D_];
__device__ __half g_qb_l[(size_t)NT_*HQ_*D_];
__device__ __half g_kb_h[(size_t)B_*T_*HKV_*D_];
__device__ __half g_kb_l[(size_t)B_*T_*HKV_*D_];
__device__ __half g_vb_h[(size_t)B_*T_*HKV_*D_];
__device__ __half g_vb_l[(size_t)B_*T_*HKV_*D_];

// ---------------- helpers ----------------------------------------------------
__device__ __forceinline__ uint32_t smem_u32(const void* p) {
    uint32_t r;
    asm("{ .reg .u64 t; cvta.to.shared.u64 t, %1; cvt.u32.u64 %0, t; }"
        : "=r"(r) : "l"(p));
    return r;
}
__device__ __forceinline__ uint16_t h_hi(float x) {
    __half h = __float2half_rn(x);
    return *reinterpret_cast<uint16_t*>(&h);
}
__device__ __forceinline__ float h_back(uint16_t u) {
    __half h = *reinterpret_cast<__half*>(&u);
    return __half2float(h);
}
__device__ __forceinline__ uint32_t pack_h2(float lo, float hi) {
    __half2 h = __floats2half2_rn(lo, hi);       // lo -> low half
    return *reinterpret_cast<uint32_t*>(&h);
}
__device__ __forceinline__ float h2lo(uint32_t p) {
    __half2 h = *reinterpret_cast<__half2*>(&p);
    return __low2float(h);
}
__device__ __forceinline__ float h2hi(uint32_t p) {
    __half2 h = *reinterpret_cast<__half2*>(&p);
    return __high2float(h);
}

#define CP_ASYNC16(dst, src) \
    asm volatile("cp.async.cg.shared.global [%0], [%1], 16;" :: "r"(dst), "l"(src))
#define CP_COMMIT() asm volatile("cp.async.commit_group;")
#define CP_WAIT2()  asm volatile("cp.async.wait_group 2;")
#define CP_WAIT1()  asm volatile("cp.async.wait_group 1;")
#define CP_WAIT0()  asm volatile("cp.async.wait_group 0;")

#define LDSM4(r, a) \
    asm volatile("ldmatrix.sync.aligned.m8n8.x4.shared.b16 {%0,%1,%2,%3}, [%4];" \
                 : "=r"((r)[0]), "=r"((r)[1]), "=r"((r)[2]), "=r"((r)[3]) : "r"(a))
#define LDSM4T(r, a) \
    asm volatile("ldmatrix.sync.aligned.m8n8.x4.trans.shared.b16 {%0,%1,%2,%3}, [%4];" \
                 : "=r"((r)[0]), "=r"((r)[1]), "=r"((r)[2]), "=r"((r)[3]) : "r"(a))

#define MMA_F16(c, a, b0v, b1v) \
    asm volatile("mma.sync.aligned.m16n8k16.row.col.f32.f16.f16.f32 " \
                 "{%0,%1,%2,%3}, {%4,%5,%6,%7}, {%8,%9}, {%0,%1,%2,%3};" \
                 : "+f"((c)[0]), "+f"((c)[1]), "+f"((c)[2]), "+f"((c)[3]) \
                 : "r"((a)[0]), "r"((a)[1]), "r"((a)[2]), "r"((a)[3]), \
                   "r"(b0v), "r"(b1v))

// ---------------- fp32 -> fp16 (hi only) -------------------------------------
__global__ void conv_h(const float4* __restrict__ in, uint2* __restrict__ oh, int n4)
{
    int i = blockIdx.x * blockDim.x + threadIdx.x;
    if (i >= n4) return;
    float4 v = in[i];
    oh[i] = make_uint2(pack_h2(v.x, v.y), pack_h2(v.z, v.w));
}

// ---------------- fp32 [K][N] -> fp16 hi/lo transposed [N][K] ----------------
__global__ void conv_splitT(const float* __restrict__ in,
                            __half* __restrict__ oh,
                            __half* __restrict__ ol, int K, int N)
{
    __shared__ float t[32][33];
    const int n0 = blockIdx.x * 32;
    const int k0 = blockIdx.y * 32;
    const int x = threadIdx.x, y = threadIdx.y;
#pragma unroll
    for (int dy = 0; dy < 4; dy++)
        t[y + dy * 8][x] = in[(size_t)(k0 + y + dy * 8) * N + n0 + x];
    __syncthreads();
#pragma unroll
    for (int dy = 0; dy < 4; dy++) {
        int nrow = y + dy * 8;
        float v = t[x][nrow];
        uint16_t h = h_hi(v);
        uint16_t l = h_hi(v - h_back(h));
        size_t o = (size_t)(n0 + nrow) * K + k0 + x;
        oh[o] = *reinterpret_cast<__half*>(&h);
        ol[o] = *reinterpret_cast<__half*>(&l);
    }
}

// ============================================================================
// fp16 2-term GEMM: C = Ah[M,K] @ (Bh+Bl)[N,K]^T.
// BM=BN=128, BK=32, 256 threads, 8 warps (2x4), warp tile 64x32.
// smem/stage: Ah 8K | Bh 8K | Bl 8K = 24KB; 3 stages.
// ============================================================================
#define GSTAGE 24576
#define GEMM_SMEM (3 * GSTAGE)

__global__ __launch_bounds__(256) void gemm_h2(
    const __half* __restrict__ Ah,
    const __half* __restrict__ Bh, const __half* __restrict__ Bl,
    float* __restrict__ C0, float* __restrict__ C1, float* __restrict__ C2,
    int n0, int n1, int ld0, int ld1, int ld2, int K)
{
    extern __shared__ char smem[];
    const uint32_t sb = smem_u32(smem);
    const int tid  = threadIdx.x;
    const int lane = tid & 31;
    const int wid  = tid >> 5;
    const int bm   = blockIdx.y * 128;
    const int bn   = blockIdx.x * 128;
    const int wm   = (wid >> 2) * 64;
    const int wn   = (wid & 3) * 32;

    const int lrow = tid >> 2;
    const int lchk = tid & 3;
    const uint32_t dsw = (uint32_t)(lrow * 64 + ((lchk ^ ((lrow >> 1) & 3)) * 16));

    // A fragment addressing (ldmatrix x4, row-major A)
    const int arow = ((lane >> 3) & 1) * 8 + (lane & 7);
    const int akc  = lane >> 4;
    const int aph  = ((lane & 7) >> 1) & 3;
    const uint32_t aBase = (uint32_t)((wm + arow) * 64);

    // B fragment addressing (ldmatrix x4 covering a j-pair)
    const int brow8 = lane & 7;
    const int bkc   = (lane >> 3) & 1;
    const int bj1   = (lane >> 4) & 1;
    const int bph   = (brow8 >> 1) & 3;
    const uint32_t bBase = (uint32_t)((wn + bj1 * 8 + brow8) * 64);

    float acc[4][4][4];
#pragma unroll
    for (int i = 0; i < 4; i++)
#pragma unroll
        for (int j = 0; j < 4; j++) {
            acc[i][j][0] = 0.f; acc[i][j][1] = 0.f;
            acc[i][j][2] = 0.f; acc[i][j][3] = 0.f;
        }

    const int nk = K / 32;

    auto issue = [&](int st, int k0) {
        const uint32_t s = sb + st * GSTAGE;
        {
            const __half* g = Ah + (size_t)(bm + lrow) * K + k0 + lchk * 8;
            uint32_t d = s + dsw;
            CP_ASYNC16(d, g);
            CP_ASYNC16(d + 4096, g + (size_t)64 * K);
        }
        {
            const __half* g = Bh + (size_t)(bn + lrow) * K + k0 + lchk * 8;
            uint32_t d = s + 8192 + dsw;
            CP_ASYNC16(d, g);
            CP_ASYNC16(d + 4096, g + (size_t)64 * K);
        }
        {
            const __half* g = Bl + (size_t)(bn + lrow) * K + k0 + lchk * 8;
            uint32_t d = s + 16384 + dsw;
            CP_ASYNC16(d, g);
            CP_ASYNC16(d + 4096, g + (size_t)64 * K);
        }
        CP_COMMIT();
    };

    issue(0, 0);
    issue(1, 32);
    issue(2, 64);

    int st = 0;
    for (int ck = 0; ck < nk; ck++) {
        const int rem = nk - 1 - ck;
        if (rem >= 2) { CP_WAIT2(); } else if (rem == 1) { CP_WAIT1(); } else { CP_WAIT0(); }
        __syncthreads();

        const uint32_t s   = sb + st * GSTAGE;
        const uint32_t sA  = s + aBase;
        const uint32_t sBH = s + 8192  + bBase;
        const uint32_t sBL = s + 16384 + bBase;

#pragma unroll
        for (int ks = 0; ks < 2; ks++) {
            const uint32_t cA = (uint32_t)(((ks * 2 + akc) ^ aph) * 16);
            const uint32_t cB = (uint32_t)(((ks * 2 + bkc) ^ bph) * 16);

            uint32_t aF[4][4];
#pragma unroll
            for (int i = 0; i < 4; i++) LDSM4(aF[i], sA + i * 1024 + cA);

            uint32_t bH[4][2], bL[4][2];
#pragma unroll
            for (int jp = 0; jp < 2; jp++) {
                uint32_t r4[4];
                LDSM4(r4, sBH + jp * 1024 + cB);
                bH[2*jp][0] = r4[0]; bH[2*jp][1] = r4[1];
                bH[2*jp+1][0] = r4[2]; bH[2*jp+1][1] = r4[3];
                LDSM4(r4, sBL + jp * 1024 + cB);
                bL[2*jp][0] = r4[0]; bL[2*jp][1] = r4[1];
                bL[2*jp+1][0] = r4[2]; bL[2*jp+1][1] = r4[3];
            }

#pragma unroll
            for (int i = 0; i < 4; i++)
#pragma unroll
                for (int j = 0; j < 4; j++)
                    MMA_F16(acc[i][j], aF[i], bH[j][0], bH[j][1]);
#pragma unroll
            for (int i = 0; i < 4; i++)
#pragma unroll
                for (int j = 0; j < 4; j++)
                    MMA_F16(acc[i][j], aF[i], bL[j][0], bL[j][1]);
        }
        __syncthreads();
        if (ck + 3 < nk) issue(st, (ck + 3) * 32);
        st = (st == 2) ? 0 : st + 1;
    }

    float* Cp;
    int ld, cbase;
    if (bn < n0)      { Cp = C0; ld = ld0; cbase = bn; }
    else if (bn < n1) { Cp = C1; ld = ld1; cbase = bn - n0; }
    else              { Cp = C2; ld = ld2; cbase = bn - n1; }

    const int g4 = lane >> 2, t4 = lane & 3;
#pragma unroll
    for (int i = 0; i < 4; i++) {
        const int row = bm + wm + i * 16 + g4;
#pragma unroll
        for (int j = 0; j < 4; j++) {
            const int col = cbase + wn + j * 8 + t4 * 2;
            *reinterpret_cast<float2*>(&Cp[(size_t)row * ld + col]) =
                make_float2(acc[i][j][0], acc[i][j][1]);
            *reinterpret_cast<float2*>(&Cp[(size_t)(row + 8) * ld + col]) =
                make_float2(acc[i][j][2], acc[i][j][3]);
        }
    }
}

// ---------------- RoPE Q -> fp16 split ---------------------------------------
__global__ void rope_q_kernel()
{
    int idx = blockIdx.x * blockDim.x + threadIdx.x;
    if (idx >= NT_ * HQ_ * 64) return;
    int d   = idx & 63;
    int th  = idx >> 6;
    int tok = th >> 5;
    int s   = tok & (S_ - 1);
    float pos = (float)(L_ + s);
    float inv = powf(THETA_, -(float)d * (1.0f / 64.0f));
    float ang = pos * inv;
    float c = cosf(ang), sn = sinf(ang);
    const float* base = g_q + (size_t)th * D_;
    float x1 = base[d], x2 = base[d + 64];
    float y1 = x1 * c - x2 * sn;
    float y2 = x2 * c + x1 * sn;
    size_t o = (size_t)th * D_;
    uint16_t h1 = h_hi(y1), h2 = h_hi(y2);
    g_qb_h[o + d]      = *reinterpret_cast<__half*>(&h1);
    g_qb_h[o + d + 64] = *reinterpret_cast<__half*>(&h2);
    uint16_t l1 = h_hi(y1 - h_back(h1)), l2 = h_hi(y2 - h_back(h2));
    g_qb_l[o + d]      = *reinterpret_cast<__half*>(&l1);
    g_qb_l[o + d + 64] = *reinterpret_cast<__half*>(&l2);
}

__global__ void rope_scatter_k_kernel()
{
    int idx = blockIdx.x * blockDim.x + threadIdx.x;
    if (idx >= NT_ * HKV_ * 64) return;
    int d   = idx & 63;
    int th  = idx >> 6;
    int tok = th >> 3;
    int kvh = th & 7;
    int b   = tok >> 9;
    int s   = tok & 511;
    float pos = (float)(L_ + s);
    float inv = powf(THETA_, -(float)d * (1.0f / 64.0f));
    float ang = pos * inv;
    float c = cosf(ang), sn = sinf(ang);
    const float* src = g_ktmp + (size_t)th * D_;
    float x1 = src[d], x2 = src[d + 64];
    float y1 = x1 * c - x2 * sn;
    float y2 = x2 * c + x1 * sn;
    size_t o = (((size_t)(b * T_ + L_ + s)) * HKV_ + kvh) * D_;
    uint16_t h1 = h_hi(y1), h2 = h_hi(y2);
    g_kb_h[o + d]      = *reinterpret_cast<__half*>(&h1);
    g_kb_h[o + d + 64] = *reinterpret_cast<__half*>(&h2);
    uint16_t l1 = h_hi(y1 - h_back(h1)), l2 = h_hi(y2 - h_back(h2));
    g_kb_l[o + d]      = *reinterpret_cast<__half*>(&l1);
    g_kb_l[o + d + 64] = *reinterpret_cast<__half*>(&l2);
}

__global__ void scatter_v_kernel()
{
    int idx = blockIdx.x * blockDim.x + threadIdx.x;
    const int n = NT_ * HKV_ * D_ / 2;
    if (idx >= n) return;
    int e   = idx * 2;
    int tok = e >> 10;
    int r   = e & 1023;
    int b   = tok >> 9;
    int s   = tok & 511;
    float2 v = reinterpret_cast<const float2*>(g_vtmp)[idx];
    uint16_t hx = h_hi(v.x), hy = h_hi(v.y);
    uint16_t lx = h_hi(v.x - h_back(hx)), ly = h_hi(v.y - h_back(hy));
    size_t o2 = ((((size_t)(b * T_ + L_ + s)) * HKV_) * D_ + r) >> 1;
    reinterpret_cast<uint32_t*>(g_vb_h)[o2] = (uint32_t)hx | ((uint32_t)hy << 16);
    reinterpret_cast<uint32_t*>(g_vb_l)[o2] = (uint32_t)lx | ((uint32_t)ly << 16);
}

__global__ void copy_cache_kernel(const float2* __restrict__ kc,
                                  const float2* __restrict__ vc)
{
    int idx = blockIdx.x * blockDim.x + threadIdx.x;
    const int n = B_ * L_ * HKV_ * D_ / 2;
    if (idx >= n) return;
    const int perb = L_ * HKV_ * D_ / 2;
    int b = idx / perb;
    size_t o2 = (size_t)idx + (size_t)b * ((T_ - L_) * HKV_ * D_ / 2);
    float2 k = kc[idx];
    float2 v = vc[idx];
    uint16_t khx = h_hi(k.x), khy = h_hi(k.y);
    uint16_t klx = h_hi(k.x - h_back(khx)), kly = h_hi(k.y - h_back(khy));
    uint16_t vhx = h_hi(v.x), vhy = h_hi(v.y);
    uint16_t vlx = h_hi(v.x - h_back(vhx)), vly = h_hi(v.y - h_back(vhy));
    reinterpret_cast<uint32_t*>(g_kb_h)[o2] = (uint32_t)khx | ((uint32_t)khy << 16);
    reinterpret_cast<uint32_t*>(g_kb_l)[o2] = (uint32_t)klx | ((uint32_t)kly << 16);
    reinterpret_cast<uint32_t*>(g_vb_h)[o2] = (uint32_t)vhx | ((uint32_t)vhy << 16);
    reinterpret_cast<uint32_t*>(g_vb_l)[o2] = (uint32_t)vlx | ((uint32_t)vly << 16);
}

// ============================================================================
// Tensor-core flash attention, fp16 3-term (structure as R5/R6)
// ============================================================================
#define AT_STAGE 65536
#define AT_SMEM  (2 * AT_STAGE)
#define SC_LOG2E 0.12751884817f

__global__ __launch_bounds__(256, 1) void attn_mma()
{
    extern __shared__ char smem[];
    const uint32_t sb = smem_u32(smem);
    const int tid  = threadIdx.x;
    const int lane = tid & 31;
    const int w    = tid >> 5;
    const int g    = lane >> 2;
    const int t4   = lane & 3;
    const int qt   = blockIdx.x;
    const int hq   = blockIdx.y;
    const int b    = blockIdx.z;
    const int kvh  = hq >> 2;

    {
        const int qr  = tid >> 1;
        const int qcb = (tid & 1) * 8;
        const size_t qo = ((size_t)(b * S_ + qt * 128 + qr)) * (HQ_ * D_) + hq * D_;
#pragma unroll
        for (int i = 0; i < 8; i++) {
            int ch = qcb + i;
            uint32_t d = sb + qr * 256 + ((ch ^ (qr & 7)) * 16);
            CP_ASYNC16(d,         g_qb_h + qo + ch * 8);
            CP_ASYNC16(d + 32768, g_qb_l + qo + ch * 8);
        }
        CP_COMMIT();
        CP_WAIT0();
    }
    __syncthreads();

    uint32_t qh[8][4], ql[8][4];
    {
        const int tt  = lane >> 3;
        const int qrow = 16 * w + (tt & 1) * 8 + (lane & 7);
        const int chi  = tt >> 1;
#pragma unroll
        for (int kk = 0; kk < 8; kk++) {
            uint32_t a = sb + qrow * 256 + (((2 * kk + chi) ^ (qrow & 7)) * 16);
            LDSM4(qh[kk], a);
            LDSM4(ql[kk], a + 32768);
        }
    }
    __syncthreads();

    const int ntiles = 26 + 2 * qt;
    const int mask_from = 24 + 2 * qt;

    auto issueKV = [&](int stage, int kt) {
        const uint32_t s = sb + stage * AT_STAGE;
        const int trow = tid >> 2;
        const int cb   = (tid & 3) * 4;
        const size_t go = (((size_t)(b * T_ + kt * 64 + trow)) * HKV_ + kvh) * D_;
        const uint32_t rb = s + trow * 256;
#pragma unroll
        for (int i = 0; i < 4; i++) {
            int ch = cb + i;
            uint32_t d = rb + ((ch ^ (trow & 7)) * 16);
            CP_ASYNC16(d,         g_kb_h + go + ch * 8);
            CP_ASYNC16(d + 16384, g_kb_l + go + ch * 8);
            CP_ASYNC16(d + 32768, g_vb_h + go + ch * 8);
            CP_ASYNC16(d + 49152, g_vb_l + go + ch * 8);
        }
        CP_COMMIT();
    };

    issueKV(0, 0);
    issueKV(1, 1);

    float oacc[16][4];
#pragma unroll
    for (int j = 0; j < 16; j++) {
        oacc[j][0] = 0.f; oacc[j][1] = 0.f; oacc[j][2] = 0.f; oacc[j][3] = 0.f;
    }
    float m0 = -1e30f, m1 = -1e30f, l0 = 0.f, l1 = 0.f;

    const int tt   = lane >> 3;
    const int krb  = (tt >> 1) * 8 + (lane & 7);
    const int kch1 = tt & 1;
    const int vrb  = (tt & 1) * 8 + (lane & 7);
    const int vch1 = tt >> 1;

    for (int kt = 0; kt < ntiles; kt++) {
        if (kt + 1 < ntiles) { CP_WAIT1(); } else { CP_WAIT0(); }
        __syncthreads();

        const uint32_t s = sb + (kt & 1) * AT_STAGE;

        float sacc[8][4];
#pragma unroll
        for (int j = 0; j < 8; j++) {
            sacc[j][0] = 0.f; sacc[j][1] = 0.f; sacc[j][2] = 0.f; sacc[j][3] = 0.f;
        }
#pragma unroll
        for (int kk = 0; kk < 8; kk++) {
#pragma unroll
            for (int jp = 0; jp < 4; jp++) {
                const int trow = jp * 16 + krb;
                const uint32_t addr = s + trow * 256 +
                                      (((2 * kk + kch1) ^ (trow & 7)) * 16);
                uint32_t bh[4], bl[4];
                LDSM4(bh, addr);
                LDSM4(bl, addr + 16384);
                MMA_F16(sacc[2*jp],   qh[kk], bh[0], bh[1]);
                MMA_F16(sacc[2*jp+1], qh[kk], bh[2], bh[3]);
                MMA_F16(sacc[2*jp],   qh[kk], bl[0], bl[1]);
                MMA_F16(sacc[2*jp+1], qh[kk], bl[2], bl[3]);
                MMA_F16(sacc[2*jp],   ql[kk], bh[0], bh[1]);
                MMA_F16(sacc[2*jp+1], ql[kk], bh[2], bh[3]);
            }
        }

        if (kt >= mask_from) {
            const int colb = kt * 64 + 2 * t4;
            const int alw0 = L_ + qt * 128 + 16 * w + g;
            const int alw1 = alw0 + 8;
#pragma unroll
            for (int j = 0; j < 8; j++) {
                int c0 = colb + j * 8;
                if (c0 > alw0)     sacc[j][0] = -1e30f;
                if (c0 + 1 > alw0) sacc[j][1] = -1e30f;
                if (c0 > alw1)     sacc[j][2] = -1e30f;
                if (c0 + 1 > alw1) sacc[j][3] = -1e30f;
            }
        }

        float rm0 = -1e30f, rm1 = -1e30f;
#pragma unroll
        for (int j = 0; j < 8; j++) {
            rm0 = fmaxf(rm0, fmaxf(sacc[j][0], sacc[j][1]));
            rm1 = fmaxf(rm1, fmaxf(sacc[j][2], sacc[j][3]));
        }
        rm0 = fmaxf(rm0, __shfl_xor_sync(0xFFFFFFFFu, rm0, 1));
        rm0 = fmaxf(rm0, __shfl_xor_sync(0xFFFFFFFFu, rm0, 2));
        rm1 = fmaxf(rm1, __shfl_xor_sync(0xFFFFFFFFu, rm1, 1));
        rm1 = fmaxf(rm1, __shfl_xor_sync(0xFFFFFFFFu, rm1, 2));

        const float nm0 = fmaxf(m0, rm0), nm1 = fmaxf(m1, rm1);
        const float f0 = exp2f((m0 - nm0) * SC_LOG2E);
        const float f1 = exp2f((m1 - nm1) * SC_LOG2E);
        float rs0 = 0.f, rs1 = 0.f;
#pragma unroll
        for (int j = 0; j < 8; j++) {
            sacc[j][0] = exp2f((sacc[j][0] - nm0) * SC_LOG2E);
            sacc[j][1] = exp2f((sacc[j][1] - nm0) * SC_LOG2E);
            sacc[j][2] = exp2f((sacc[j][2] - nm1) * SC_LOG2E);
            sacc[j][3] = exp2f((sacc[j][3] - nm1) * SC_LOG2E);
            rs0 += sacc[j][0] + sacc[j][1];
            rs1 += sacc[j][2] + sacc[j][3];
        }
        rs0 += __shfl_xor_sync(0xFFFFFFFFu, rs0, 1);
        rs0 += __shfl_xor_sync(0xFFFFFFFFu, rs0, 2);
        rs1 += __shfl_xor_sync(0xFFFFFFFFu, rs1, 1);
        rs1 += __shfl_xor_sync(0xFFFFFFFFu, rs1, 2);
        l0 = l0 * f0 + rs0;
        l1 = l1 * f1 + rs1;
        m0 = nm0; m1 = nm1;

#pragma unroll
        for (int j = 0; j < 16; j++) {
            oacc[j][0] *= f0; oacc[j][1] *= f0;
            oacc[j][2] *= f1; oacc[j][3] *= f1;
        }

        uint32_t ph[4][4], pl[4][4];
#pragma unroll
        for (int kc = 0; kc < 4; kc++) {
            float v00 = sacc[2*kc][0],   v01 = sacc[2*kc][1];
            float v02 = sacc[2*kc][2],   v03 = sacc[2*kc][3];
            float v10 = sacc[2*kc+1][0], v11 = sacc[2*kc+1][1];
            float v12 = sacc[2*kc+1][2], v13 = sacc[2*kc+1][3];
            ph[kc][0] = pack_h2(v00, v01);
            ph[kc][1] = pack_h2(v02, v03);
            ph[kc][2] = pack_h2(v10, v11);
            ph[kc][3] = pack_h2(v12, v13);
            pl[kc][0] = pack_h2(v00 - h2lo(ph[kc][0]), v01 - h2hi(ph[kc][0]));
            pl[kc][1] = pack_h2(v02 - h2lo(ph[kc][1]), v03 - h2hi(ph[kc][1]));
            pl[kc][2] = pack_h2(v10 - h2lo(ph[kc][2]), v11 - h2hi(ph[kc][2]));
            pl[kc][3] = pack_h2(v12 - h2lo(ph[kc][3]), v13 - h2hi(ph[kc][3]));
        }

        const uint32_t vbase = s + 32768;
#pragma unroll
        for (int jp2 = 0; jp2 < 8; jp2++) {
#pragma unroll
            for (int kc = 0; kc < 4; kc++) {
                const int trow = kc * 16 + vrb;
                const uint32_t addr = vbase + trow * 256 +
                                      (((jp2 * 2 + vch1) ^ (trow & 7)) * 16);
                uint32_t vh[4], vl[4];
                LDSM4T(vh, addr);
                LDSM4T(vl, addr + 16384);
                MMA_F16(oacc[2*jp2],   ph[kc], vh[0], vh[1]);
                MMA_F16(oacc[2*jp2+1], ph[kc], vh[2], vh[3]);
                MMA_F16(oacc[2*jp2],   ph[kc], vl[0], vl[1]);
                MMA_F16(oacc[2*jp2+1], ph[kc], vl[2], vl[3]);
                MMA_F16(oacc[2*jp2],   pl[kc], vh[0], vh[1]);
                MMA_F16(oacc[2*jp2+1], pl[kc], vh[2], vh[3]);
            }
        }

        __syncthreads();
        if (kt + 2 < ntiles) issueKV(kt & 1, kt + 2);
    }

    // epilogue: write fp16 hi only (O-proj A operand)
    const float il0 = 1.0f / l0;
    const float il1 = 1.0f / l1;
    const size_t tok0 = (size_t)(b * S_ + qt * 128 + 16 * w + g);
    uint32_t* oh32 = reinterpret_cast<uint32_t*>(g_attb_h);
#pragma unroll
    for (int jn = 0; jn < 16; jn++) {
        float o0 = oacc[jn][0] * il0, o1 = oacc[jn][1] * il0;
        float o2 = oacc[jn][2] * il1, o3 = oacc[jn][3] * il1;
        const size_t a0 = (tok0 * (HQ_ * D_) + hq * D_ + jn * 8 + 2 * t4) >> 1;
        const size_t a1 = a0 + (8 * (HQ_ * D_) >> 1);
        oh32[a0] = pack_h2(o0, o1);
        oh32[a1] = pack_h2(o2, o3);
    }
}

// ---------------- launcher ---------------------------------------------------
extern "C" void kernel_launch(void* const* d_in, const int* in_sizes, int n_in,
                              void* d_out, int out_size)
{
    const float* hidden  = (const float*)d_in[0];
    const float* k_cache = (const float*)d_in[1];
    const float* v_cache = (const float*)d_in[2];
    const float* wq      = (const float*)d_in[3];
    const float* wk      = (const float*)d_in[4];
    const float* wv      = (const float*)d_in[5];
    const float* wo      = (const float*)d_in[6];
    float* out = (float*)d_out;

    float *q, *ktmp, *vtmp;
    cudaGetSymbolAddress((void**)&q,    g_q);
    cudaGetSymbolAddress((void**)&ktmp, g_ktmp);
    cudaGetSymbolAddress((void**)&vtmp, g_vtmp);

    __half *hid_h, *wqkv_h, *wqkv_l, *wo_h, *wo_l, *attb_h;
    cudaGetSymbolAddress((void**)&hid_h,  g_hid_h);
    cudaGetSymbolAddress((void**)&wqkv_h, g_wqkvT_h);
    cudaGetSymbolAddress((void**)&wqkv_l, g_wqkvT_l);
    cudaGetSymbolAddress((void**)&wo_h,   g_woT_h);
    cudaGetSymbolAddress((void**)&wo_l,   g_woT_l);
    cudaGetSymbolAddress((void**)&attb_h, g_attb_h);

    cudaFuncSetAttribute(gemm_h2,
                         cudaFuncAttributeMaxDynamicSharedMemorySize, GEMM_SMEM);
    cudaFuncSetAttribute(attn_mma,
                         cudaFuncAttributeMaxDynamicSharedMemorySize, AT_SMEM);

    // conversions
    conv_h<<<(NT_ * H_ / 4 + 255) / 256, 256>>>(
        (const float4*)hidden, (uint2*)hid_h, NT_ * H_ / 4);
    conv_splitT<<<dim3(H_ / 32, H_ / 32), dim3(32, 8)>>>(wq, wqkv_h, wqkv_l, H_, H_);
    conv_splitT<<<dim3((HKV_ * D_) / 32, H_ / 32), dim3(32, 8)>>>(
        wk, wqkv_h + (size_t)H_ * H_, wqkv_l + (size_t)H_ * H_, H_, HKV_ * D_);
    conv_splitT<<<dim3((HKV_ * D_) / 32, H_ / 32), dim3(32, 8)>>>(
        wv, wqkv_h + (size_t)(H_ + HKV_ * D_) * H_, wqkv_l + (size_t)(H_ + HKV_ * D_) * H_,
        H_, HKV_ * D_);
    conv_splitT<<<dim3(H_ / 32, H_ / 32), dim3(32, 8)>>>(wo, wo_h, wo_l, H_, H_);

    // fused QKV projection
    gemm_h2<<<dim3(NQKV / 128, NT_ / 128), 256, GEMM_SMEM>>>(
        hid_h, wqkv_h, wqkv_l,
        q, ktmp, vtmp, H_, H_ + HKV_ * D_, H_, HKV_ * D_, HKV_ * D_, H_);

    // rope + KV assembly
    rope_q_kernel<<<(NT_ * HQ_ * 64) / 256, 256>>>();
    rope_scatter_k_kernel<<<(NT_ * HKV_ * 64) / 256, 256>>>();
    scatter_v_kernel<<<(NT_ * HKV_ * D_ / 2) / 256, 256>>>();
    copy_cache_kernel<<<(B_ * L_ * HKV_ * D_ / 2) / 256, 256>>>(
        (const float2*)k_cache, (const float2*)v_cache);

    // attention
    attn_mma<<<dim3(S_ / 128, HQ_, B_), 256, AT_SMEM>>>();

    // output projection
    gemm_h2<<<dim3(H_ / 128, NT_ / 128), 256, GEMM_SMEM>>>(
        attb_h, wo_h, wo_l,
        out, out, out, H_, H_, H_, H_, H_, H_);
}

// round 8
// speedup vs baseline: 1.7619x; 1.3574x over previous
#include <cuda_runtime.h>
#include <cuda_fp16.h>
#include <math.h>
#include <stdint.h>

// Problem constants
#define B_    8
#define S_    512
#define H_    4096
#define HQ_   32
#define HKV_  8
#define D_    128
#define L_    1536
#define T_    2048
#define NT_   (B_*S_)
#define THETA_ 500000.0f
#define NQKV  (H_ + 2*HKV_*D_)      // 6144

// ---------------- scratch (device globals) ----------------------------------
__device__ float g_q   [(size_t)NT_*HQ_ *D_];
__device__ float g_ktmp[(size_t)NT_*HKV_*D_];
__device__ float g_vtmp[(size_t)NT_*HKV_*D_];

__device__ __half g_hid_h [(size_t)NT_*H_];
__device__ __half g_wqkvT_h[(size_t)NQKV*H_];
__device__ __half g_woT_h [(size_t)H_*H_];
__device__ __half g_attb_h[(size_t)NT_*H_];

__device__ __half g_qb_h[(size_t)NT_*HQ_*D_];
__device__ __half g_qb_l[(size_t)NT_*HQ_*D_];
__device__ __half g_kb_h[(size_t)B_*T_*HKV_*D_];
__device__ __half g_kb_l[(size_t)B_*T_*HKV_*D_];
__device__ __half g_vb_h[(size_t)B_*T_*HKV_*D_];
__device__ __half g_vb_l[(size_t)B_*T_*HKV_*D_];

// ---------------- helpers ----------------------------------------------------
__device__ __forceinline__ uint32_t smem_u32(const void* p) {
    uint32_t r;
    asm("{ .reg .u64 t; cvta.to.shared.u64 t, %1; cvt.u32.u64 %0, t; }"
        : "=r"(r) : "l"(p));
    return r;
}
__device__ __forceinline__ uint16_t h_hi(float x) {
    __half h = __float2half_rn(x);
    return *reinterpret_cast<uint16_t*>(&h);
}
__device__ __forceinline__ float h_back(uint16_t u) {
    __half h = *reinterpret_cast<__half*>(&u);
    return __half2float(h);
}
__device__ __forceinline__ uint32_t pack_h2(float lo, float hi) {
    __half2 h = __floats2half2_rn(lo, hi);       // lo -> low half
    return *reinterpret_cast<uint32_t*>(&h);
}
__device__ __forceinline__ float h2lo(uint32_t p) {
    __half2 h = *reinterpret_cast<__half2*>(&p);
    return __low2float(h);
}
__device__ __forceinline__ float h2hi(uint32_t p) {
    __half2 h = *reinterpret_cast<__half2*>(&p);
    return __high2float(h);
}

#define CP_ASYNC16(dst, src) \
    asm volatile("cp.async.cg.shared.global [%0], [%1], 16;" :: "r"(dst), "l"(src))
#define CP_COMMIT() asm volatile("cp.async.commit_group;")
#define CP_WAIT2()  asm volatile("cp.async.wait_group 2;")
#define CP_WAIT1()  asm volatile("cp.async.wait_group 1;")
#define CP_WAIT0()  asm volatile("cp.async.wait_group 0;")

#define LDSM4(r, a) \
    asm volatile("ldmatrix.sync.aligned.m8n8.x4.shared.b16 {%0,%1,%2,%3}, [%4];" \
                 : "=r"((r)[0]), "=r"((r)[1]), "=r"((r)[2]), "=r"((r)[3]) : "r"(a))
#define LDSM4T(r, a) \
    asm volatile("ldmatrix.sync.aligned.m8n8.x4.trans.shared.b16 {%0,%1,%2,%3}, [%4];" \
                 : "=r"((r)[0]), "=r"((r)[1]), "=r"((r)[2]), "=r"((r)[3]) : "r"(a))

#define MMA_F16(c, a, b0v, b1v) \
    asm volatile("mma.sync.aligned.m16n8k16.row.col.f32.f16.f16.f32 " \
                 "{%0,%1,%2,%3}, {%4,%5,%6,%7}, {%8,%9}, {%0,%1,%2,%3};" \
                 : "+f"((c)[0]), "+f"((c)[1]), "+f"((c)[2]), "+f"((c)[3]) \
                 : "r"((a)[0]), "r"((a)[1]), "r"((a)[2]), "r"((a)[3]), \
                   "r"(b0v), "r"(b1v))

// ---------------- fp32 -> fp16 (hi only) -------------------------------------
__global__ void conv_h(const float4* __restrict__ in, uint2* __restrict__ oh, int n4)
{
    int i = blockIdx.x * blockDim.x + threadIdx.x;
    if (i >= n4) return;
    float4 v = in[i];
    oh[i] = make_uint2(pack_h2(v.x, v.y), pack_h2(v.z, v.w));
}

// ---------------- fp32 [K][N] -> fp16 transposed [N][K] (hi only) ------------
__global__ void conv_hT(const float* __restrict__ in,
                        __half* __restrict__ oh, int K, int N)
{
    __shared__ float t[32][33];
    const int n0 = blockIdx.x * 32;
    const int k0 = blockIdx.y * 32;
    const int x = threadIdx.x, y = threadIdx.y;
#pragma unroll
    for (int dy = 0; dy < 4; dy++)
        t[y + dy * 8][x] = in[(size_t)(k0 + y + dy * 8) * N + n0 + x];
    __syncthreads();
#pragma unroll
    for (int dy = 0; dy < 4; dy++) {
        int nrow = y + dy * 8;
        float v = t[x][nrow];
        uint16_t h = h_hi(v);
        oh[(size_t)(n0 + nrow) * K + k0 + x] = *reinterpret_cast<__half*>(&h);
    }
}

// ============================================================================
// fp16 1-term GEMM: C = Ah[M,K] @ Bh[N,K]^T.
// BM=BN=128, BK=32, 256 threads, 8 warps (2x4), warp tile 64x32.
// smem/stage: Ah 8K | Bh 8K = 16KB; 3 stages.
// ============================================================================
#define GSTAGE 16384
#define GEMM_SMEM (3 * GSTAGE)

__global__ __launch_bounds__(256) void gemm_h1(
    const __half* __restrict__ Ah, const __half* __restrict__ Bh,
    float* __restrict__ C0, float* __restrict__ C1, float* __restrict__ C2,
    int n0, int n1, int ld0, int ld1, int ld2, int K)
{
    extern __shared__ char smem[];
    const uint32_t sb = smem_u32(smem);
    const int tid  = threadIdx.x;
    const int lane = tid & 31;
    const int wid  = tid >> 5;
    const int bm   = blockIdx.y * 128;
    const int bn   = blockIdx.x * 128;
    const int wm   = (wid >> 2) * 64;
    const int wn   = (wid & 3) * 32;

    const int lrow = tid >> 2;
    const int lchk = tid & 3;
    const uint32_t dsw = (uint32_t)(lrow * 64 + ((lchk ^ ((lrow >> 1) & 3)) * 16));

    // A fragment addressing
    const int arow = ((lane >> 3) & 1) * 8 + (lane & 7);
    const int akc  = lane >> 4;
    const int aph  = ((lane & 7) >> 1) & 3;
    const uint32_t aBase = (uint32_t)((wm + arow) * 64);

    // B fragment addressing (x4 covers a j-pair)
    const int brow8 = lane & 7;
    const int bkc   = (lane >> 3) & 1;
    const int bj1   = (lane >> 4) & 1;
    const int bph   = (brow8 >> 1) & 3;
    const uint32_t bBase = (uint32_t)((wn + bj1 * 8 + brow8) * 64);

    float acc[4][4][4];
#pragma unroll
    for (int i = 0; i < 4; i++)
#pragma unroll
        for (int j = 0; j < 4; j++) {
            acc[i][j][0] = 0.f; acc[i][j][1] = 0.f;
            acc[i][j][2] = 0.f; acc[i][j][3] = 0.f;
        }

    const int nk = K / 32;

    auto issue = [&](int st, int k0) {
        const uint32_t s = sb + st * GSTAGE;
        {
            const __half* g = Ah + (size_t)(bm + lrow) * K + k0 + lchk * 8;
            uint32_t d = s + dsw;
            CP_ASYNC16(d, g);
            CP_ASYNC16(d + 4096, g + (size_t)64 * K);
        }
        {
            const __half* g = Bh + (size_t)(bn + lrow) * K + k0 + lchk * 8;
            uint32_t d = s + 8192 + dsw;
            CP_ASYNC16(d, g);
            CP_ASYNC16(d + 4096, g + (size_t)64 * K);
        }
        CP_COMMIT();
    };

    issue(0, 0);
    issue(1, 32);
    issue(2, 64);

    int st = 0;
    for (int ck = 0; ck < nk; ck++) {
        const int rem = nk - 1 - ck;
        if (rem >= 2) { CP_WAIT2(); } else if (rem == 1) { CP_WAIT1(); } else { CP_WAIT0(); }
        __syncthreads();

        const uint32_t s   = sb + st * GSTAGE;
        const uint32_t sA  = s + aBase;
        const uint32_t sBH = s + 8192 + bBase;

#pragma unroll
        for (int ks = 0; ks < 2; ks++) {
            const uint32_t cA = (uint32_t)(((ks * 2 + akc) ^ aph) * 16);
            const uint32_t cB = (uint32_t)(((ks * 2 + bkc) ^ bph) * 16);

            uint32_t aF[4][4];
#pragma unroll
            for (int i = 0; i < 4; i++) LDSM4(aF[i], sA + i * 1024 + cA);

            uint32_t bH[4][2];
#pragma unroll
            for (int jp = 0; jp < 2; jp++) {
                uint32_t r4[4];
                LDSM4(r4, sBH + jp * 1024 + cB);
                bH[2*jp][0] = r4[0]; bH[2*jp][1] = r4[1];
                bH[2*jp+1][0] = r4[2]; bH[2*jp+1][1] = r4[3];
            }

#pragma unroll
            for (int i = 0; i < 4; i++)
#pragma unroll
                for (int j = 0; j < 4; j++)
                    MMA_F16(acc[i][j], aF[i], bH[j][0], bH[j][1]);
        }
        __syncthreads();
        if (ck + 3 < nk) issue(st, (ck + 3) * 32);
        st = (st == 2) ? 0 : st + 1;
    }

    float* Cp;
    int ld, cbase;
    if (bn < n0)      { Cp = C0; ld = ld0; cbase = bn; }
    else if (bn < n1) { Cp = C1; ld = ld1; cbase = bn - n0; }
    else              { Cp = C2; ld = ld2; cbase = bn - n1; }

    const int g4 = lane >> 2, t4 = lane & 3;
#pragma unroll
    for (int i = 0; i < 4; i++) {
        const int row = bm + wm + i * 16 + g4;
#pragma unroll
        for (int j = 0; j < 4; j++) {
            const int col = cbase + wn + j * 8 + t4 * 2;
            *reinterpret_cast<float2*>(&Cp[(size_t)row * ld + col]) =
                make_float2(acc[i][j][0], acc[i][j][1]);
            *reinterpret_cast<float2*>(&Cp[(size_t)(row + 8) * ld + col]) =
                make_float2(acc[i][j][2], acc[i][j][3]);
        }
    }
}

// ---------------- RoPE Q -> fp16 split ---------------------------------------
__global__ void rope_q_kernel()
{
    int idx = blockIdx.x * blockDim.x + threadIdx.x;
    if (idx >= NT_ * HQ_ * 64) return;
    int d   = idx & 63;
    int th  = idx >> 6;
    int tok = th >> 5;
    int s   = tok & (S_ - 1);
    float pos = (float)(L_ + s);
    float inv = powf(THETA_, -(float)d * (1.0f / 64.0f));
    float ang = pos * inv;
    float c = cosf(ang), sn = sinf(ang);
    const float* base = g_q + (size_t)th * D_;
    float x1 = base[d], x2 = base[d + 64];
    float y1 = x1 * c - x2 * sn;
    float y2 = x2 * c + x1 * sn;
    size_t o = (size_t)th * D_;
    uint16_t h1 = h_hi(y1), h2 = h_hi(y2);
    g_qb_h[o + d]      = *reinterpret_cast<__half*>(&h1);
    g_qb_h[o + d + 64] = *reinterpret_cast<__half*>(&h2);
    uint16_t l1 = h_hi(y1 - h_back(h1)), l2 = h_hi(y2 - h_back(h2));
    g_qb_l[o + d]      = *reinterpret_cast<__half*>(&l1);
    g_qb_l[o + d + 64] = *reinterpret_cast<__half*>(&l2);
}

__global__ void rope_scatter_k_kernel()
{
    int idx = blockIdx.x * blockDim.x + threadIdx.x;
    if (idx >= NT_ * HKV_ * 64) return;
    int d   = idx & 63;
    int th  = idx >> 6;
    int tok = th >> 3;
    int kvh = th & 7;
    int b   = tok >> 9;
    int s   = tok & 511;
    float pos = (float)(L_ + s);
    float inv = powf(THETA_, -(float)d * (1.0f / 64.0f));
    float ang = pos * inv;
    float c = cosf(ang), sn = sinf(ang);
    const float* src = g_ktmp + (size_t)th * D_;
    float x1 = src[d], x2 = src[d + 64];
    float y1 = x1 * c - x2 * sn;
    float y2 = x2 * c + x1 * sn;
    size_t o = (((size_t)(b * T_ + L_ + s)) * HKV_ + kvh) * D_;
    uint16_t h1 = h_hi(y1), h2 = h_hi(y2);
    g_kb_h[o + d]      = *reinterpret_cast<__half*>(&h1);
    g_kb_h[o + d + 64] = *reinterpret_cast<__half*>(&h2);
    uint16_t l1 = h_hi(y1 - h_back(h1)), l2 = h_hi(y2 - h_back(h2));
    g_kb_l[o + d]      = *reinterpret_cast<__half*>(&l1);
    g_kb_l[o + d + 64] = *reinterpret_cast<__half*>(&l2);
}

__global__ void scatter_v_kernel()
{
    int idx = blockIdx.x * blockDim.x + threadIdx.x;
    const int n = NT_ * HKV_ * D_ / 2;
    if (idx >= n) return;
    int e   = idx * 2;
    int tok = e >> 10;
    int r   = e & 1023;
    int b   = tok >> 9;
    int s   = tok & 511;
    float2 v = reinterpret_cast<const float2*>(g_vtmp)[idx];
    uint16_t hx = h_hi(v.x), hy = h_hi(v.y);
    uint16_t lx = h_hi(v.x - h_back(hx)), ly = h_hi(v.y - h_back(hy));
    size_t o2 = ((((size_t)(b * T_ + L_ + s)) * HKV_) * D_ + r) >> 1;
    reinterpret_cast<uint32_t*>(g_vb_h)[o2] = (uint32_t)hx | ((uint32_t)hy << 16);
    reinterpret_cast<uint32_t*>(g_vb_l)[o2] = (uint32_t)lx | ((uint32_t)ly << 16);
}

__global__ void copy_cache_kernel(const float2* __restrict__ kc,
                                  const float2* __restrict__ vc)
{
    int idx = blockIdx.x * blockDim.x + threadIdx.x;
    const int n = B_ * L_ * HKV_ * D_ / 2;
    if (idx >= n) return;
    const int perb = L_ * HKV_ * D_ / 2;
    int b = idx / perb;
    size_t o2 = (size_t)idx + (size_t)b * ((T_ - L_) * HKV_ * D_ / 2);
    float2 k = kc[idx];
    float2 v = vc[idx];
    uint16_t khx = h_hi(k.x), khy = h_hi(k.y);
    uint16_t klx = h_hi(k.x - h_back(khx)), kly = h_hi(k.y - h_back(khy));
    uint16_t vhx = h_hi(v.x), vhy = h_hi(v.y);
    uint16_t vlx = h_hi(v.x - h_back(vhx)), vly = h_hi(v.y - h_back(vhy));
    reinterpret_cast<uint32_t*>(g_kb_h)[o2] = (uint32_t)khx | ((uint32_t)khy << 16);
    reinterpret_cast<uint32_t*>(g_kb_l)[o2] = (uint32_t)klx | ((uint32_t)kly << 16);
    reinterpret_cast<uint32_t*>(g_vb_h)[o2] = (uint32_t)vhx | ((uint32_t)vhy << 16);
    reinterpret_cast<uint32_t*>(g_vb_l)[o2] = (uint32_t)vlx | ((uint32_t)vly << 16);
}

// ============================================================================
// Tensor-core flash attention, fp16 3-term (unchanged from R7)
// ============================================================================
#define AT_STAGE 65536
#define AT_SMEM  (2 * AT_STAGE)
#define SC_LOG2E 0.12751884817f

__global__ __launch_bounds__(256, 1) void attn_mma()
{
    extern __shared__ char smem[];
    const uint32_t sb = smem_u32(smem);
    const int tid  = threadIdx.x;
    const int lane = tid & 31;
    const int w    = tid >> 5;
    const int g    = lane >> 2;
    const int t4   = lane & 3;
    const int qt   = blockIdx.x;
    const int hq   = blockIdx.y;
    const int b    = blockIdx.z;
    const int kvh  = hq >> 2;

    {
        const int qr  = tid >> 1;
        const int qcb = (tid & 1) * 8;
        const size_t qo = ((size_t)(b * S_ + qt * 128 + qr)) * (HQ_ * D_) + hq * D_;
#pragma unroll
        for (int i = 0; i < 8; i++) {
            int ch = qcb + i;
            uint32_t d = sb + qr * 256 + ((ch ^ (qr & 7)) * 16);
            CP_ASYNC16(d,         g_qb_h + qo + ch * 8);
            CP_ASYNC16(d + 32768, g_qb_l + qo + ch * 8);
        }
        CP_COMMIT();
        CP_WAIT0();
    }
    __syncthreads();

    uint32_t qh[8][4], ql[8][4];
    {
        const int tt  = lane >> 3;
        const int qrow = 16 * w + (tt & 1) * 8 + (lane & 7);
        const int chi  = tt >> 1;
#pragma unroll
        for (int kk = 0; kk < 8; kk++) {
            uint32_t a = sb + qrow * 256 + (((2 * kk + chi) ^ (qrow & 7)) * 16);
            LDSM4(qh[kk], a);
            LDSM4(ql[kk], a + 32768);
        }
    }
    __syncthreads();

    const int ntiles = 26 + 2 * qt;
    const int mask_from = 24 + 2 * qt;

    auto issueKV = [&](int stage, int kt) {
        const uint32_t s = sb + stage * AT_STAGE;
        const int trow = tid >> 2;
        const int cb   = (tid & 3) * 4;
        const size_t go = (((size_t)(b * T_ + kt * 64 + trow)) * HKV_ + kvh) * D_;
        const uint32_t rb = s + trow * 256;
#pragma unroll
        for (int i = 0; i < 4; i++) {
            int ch = cb + i;
            uint32_t d = rb + ((ch ^ (trow & 7)) * 16);
            CP_ASYNC16(d,         g_kb_h + go + ch * 8);
            CP_ASYNC16(d + 16384, g_kb_l + go + ch * 8);
            CP_ASYNC16(d + 32768, g_vb_h + go + ch * 8);
            CP_ASYNC16(d + 49152, g_vb_l + go + ch * 8);
        }
        CP_COMMIT();
    };

    issueKV(0, 0);
    issueKV(1, 1);

    float oacc[16][4];
#pragma unroll
    for (int j = 0; j < 16; j++) {
        oacc[j][0] = 0.f; oacc[j][1] = 0.f; oacc[j][2] = 0.f; oacc[j][3] = 0.f;
    }
    float m0 = -1e30f, m1 = -1e30f, l0 = 0.f, l1 = 0.f;

    const int tt   = lane >> 3;
    const int krb  = (tt >> 1) * 8 + (lane & 7);
    const int kch1 = tt & 1;
    const int vrb  = (tt & 1) * 8 + (lane & 7);
    const int vch1 = tt >> 1;

    for (int kt = 0; kt < ntiles; kt++) {
        if (kt + 1 < ntiles) { CP_WAIT1(); } else { CP_WAIT0(); }
        __syncthreads();

        const uint32_t s = sb + (kt & 1) * AT_STAGE;

        float sacc[8][4];
#pragma unroll
        for (int j = 0; j < 8; j++) {
            sacc[j][0] = 0.f; sacc[j][1] = 0.f; sacc[j][2] = 0.f; sacc[j][3] = 0.f;
        }
#pragma unroll
        for (int kk = 0; kk < 8; kk++) {
#pragma unroll
            for (int jp = 0; jp < 4; jp++) {
                const int trow = jp * 16 + krb;
                const uint32_t addr = s + trow * 256 +
                                      (((2 * kk + kch1) ^ (trow & 7)) * 16);
                uint32_t bh[4], bl[4];
                LDSM4(bh, addr);
                LDSM4(bl, addr + 16384);
                MMA_F16(sacc[2*jp],   qh[kk], bh[0], bh[1]);
                MMA_F16(sacc[2*jp+1], qh[kk], bh[2], bh[3]);
                MMA_F16(sacc[2*jp],   qh[kk], bl[0], bl[1]);
                MMA_F16(sacc[2*jp+1], qh[kk], bl[2], bl[3]);
                MMA_F16(sacc[2*jp],   ql[kk], bh[0], bh[1]);
                MMA_F16(sacc[2*jp+1], ql[kk], bh[2], bh[3]);
            }
        }

        if (kt >= mask_from) {
            const int colb = kt * 64 + 2 * t4;
            const int alw0 = L_ + qt * 128 + 16 * w + g;
            const int alw1 = alw0 + 8;
#pragma unroll
            for (int j = 0; j < 8; j++) {
                int c0 = colb + j * 8;
                if (c0 > alw0)     sacc[j][0] = -1e30f;
                if (c0 + 1 > alw0) sacc[j][1] = -1e30f;
                if (c0 > alw1)     sacc[j][2] = -1e30f;
                if (c0 + 1 > alw1) sacc[j][3] = -1e30f;
            }
        }

        float rm0 = -1e30f, rm1 = -1e30f;
#pragma unroll
        for (int j = 0; j < 8; j++) {
            rm0 = fmaxf(rm0, fmaxf(sacc[j][0], sacc[j][1]));
            rm1 = fmaxf(rm1, fmaxf(sacc[j][2], sacc[j][3]));
        }
        rm0 = fmaxf(rm0, __shfl_xor_sync(0xFFFFFFFFu, rm0, 1));
        rm0 = fmaxf(rm0, __shfl_xor_sync(0xFFFFFFFFu, rm0, 2));
        rm1 = fmaxf(rm1, __shfl_xor_sync(0xFFFFFFFFu, rm1, 1));
        rm1 = fmaxf(rm1, __shfl_xor_sync(0xFFFFFFFFu, rm1, 2));

        const float nm0 = fmaxf(m0, rm0), nm1 = fmaxf(m1, rm1);
        const float f0 = exp2f((m0 - nm0) * SC_LOG2E);
        const float f1 = exp2f((m1 - nm1) * SC_LOG2E);
        float rs0 = 0.f, rs1 = 0.f;
#pragma unroll
        for (int j = 0; j < 8; j++) {
            sacc[j][0] = exp2f((sacc[j][0] - nm0) * SC_LOG2E);
            sacc[j][1] = exp2f((sacc[j][1] - nm0) * SC_LOG2E);
            sacc[j][2] = exp2f((sacc[j][2] - nm1) * SC_LOG2E);
            sacc[j][3] = exp2f((sacc[j][3] - nm1) * SC_LOG2E);
            rs0 += sacc[j][0] + sacc[j][1];
            rs1 += sacc[j][2] + sacc[j][3];
        }
        rs0 += __shfl_xor_sync(0xFFFFFFFFu, rs0, 1);
        rs0 += __shfl_xor_sync(0xFFFFFFFFu, rs0, 2);
        rs1 += __shfl_xor_sync(0xFFFFFFFFu, rs1, 1);
        rs1 += __shfl_xor_sync(0xFFFFFFFFu, rs1, 2);
        l0 = l0 * f0 + rs0;
        l1 = l1 * f1 + rs1;
        m0 = nm0; m1 = nm1;

#pragma unroll
        for (int j = 0; j < 16; j++) {
            oacc[j][0] *= f0; oacc[j][1] *= f0;
            oacc[j][2] *= f1; oacc[j][3] *= f1;
        }

        uint32_t ph[4][4], pl[4][4];
#pragma unroll
        for (int kc = 0; kc < 4; kc++) {
            float v00 = sacc[2*kc][0],   v01 = sacc[2*kc][1];
            float v02 = sacc[2*kc][2],   v03 = sacc[2*kc][3];
            float v10 = sacc[2*kc+1][0], v11 = sacc[2*kc+1][1];
            float v12 = sacc[2*kc+1][2], v13 = sacc[2*kc+1][3];
            ph[kc][0] = pack_h2(v00, v01);
            ph[kc][1] = pack_h2(v02, v03);
            ph[kc][2] = pack_h2(v10, v11);
            ph[kc][3] = pack_h2(v12, v13);
            pl[kc][0] = pack_h2(v00 - h2lo(ph[kc][0]), v01 - h2hi(ph[kc][0]));
            pl[kc][1] = pack_h2(v02 - h2lo(ph[kc][1]), v03 - h2hi(ph[kc][1]));
            pl[kc][2] = pack_h2(v10 - h2lo(ph[kc][2]), v11 - h2hi(ph[kc][2]));
            pl[kc][3] = pack_h2(v12 - h2lo(ph[kc][3]), v13 - h2hi(ph[kc][3]));
        }

        const uint32_t vbase = s + 32768;
#pragma unroll
        for (int jp2 = 0; jp2 < 8; jp2++) {
#pragma unroll
            for (int kc = 0; kc < 4; kc++) {
                const int trow = kc * 16 + vrb;
                const uint32_t addr = vbase + trow * 256 +
                                      (((jp2 * 2 + vch1) ^ (trow & 7)) * 16);
                uint32_t vh[4], vl[4];
                LDSM4T(vh, addr);
                LDSM4T(vl, addr + 16384);
                MMA_F16(oacc[2*jp2],   ph[kc], vh[0], vh[1]);
                MMA_F16(oacc[2*jp2+1], ph[kc], vh[2], vh[3]);
                MMA_F16(oacc[2*jp2],   ph[kc], vl[0], vl[1]);
                MMA_F16(oacc[2*jp2+1], ph[kc], vl[2], vl[3]);
                MMA_F16(oacc[2*jp2],   pl[kc], vh[0], vh[1]);
                MMA_F16(oacc[2*jp2+1], pl[kc], vh[2], vh[3]);
            }
        }

        __syncthreads();
        if (kt + 2 < ntiles) issueKV(kt & 1, kt + 2);
    }

    const float il0 = 1.0f / l0;
    const float il1 = 1.0f / l1;
    const size_t tok0 = (size_t)(b * S_ + qt * 128 + 16 * w + g);
    uint32_t* oh32 = reinterpret_cast<uint32_t*>(g_attb_h);
#pragma unroll
    for (int jn = 0; jn < 16; jn++) {
        float o0 = oacc[jn][0] * il0, o1 = oacc[jn][1] * il0;
        float o2 = oacc[jn][2] * il1, o3 = oacc[jn][3] * il1;
        const size_t a0 = (tok0 * (HQ_ * D_) + hq * D_ + jn * 8 + 2 * t4) >> 1;
        const size_t a1 = a0 + (8 * (HQ_ * D_) >> 1);
        oh32[a0] = pack_h2(o0, o1);
        oh32[a1] = pack_h2(o2, o3);
    }
}

// ---------------- launcher ---------------------------------------------------
extern "C" void kernel_launch(void* const* d_in, const int* in_sizes, int n_in,
                              void* d_out, int out_size)
{
    const float* hidden  = (const float*)d_in[0];
    const float* k_cache = (const float*)d_in[1];
    const float* v_cache = (const float*)d_in[2];
    const float* wq      = (const float*)d_in[3];
    const float* wk      = (const float*)d_in[4];
    const float* wv      = (const float*)d_in[5];
    const float* wo      = (const float*)d_in[6];
    float* out = (float*)d_out;

    float *q, *ktmp, *vtmp;
    cudaGetSymbolAddress((void**)&q,    g_q);
    cudaGetSymbolAddress((void**)&ktmp, g_ktmp);
    cudaGetSymbolAddress((void**)&vtmp, g_vtmp);

    __half *hid_h, *wqkv_h, *wo_h, *attb_h;
    cudaGetSymbolAddress((void**)&hid_h,  g_hid_h);
    cudaGetSymbolAddress((void**)&wqkv_h, g_wqkvT_h);
    cudaGetSymbolAddress((void**)&wo_h,   g_woT_h);
    cudaGetSymbolAddress((void**)&attb_h, g_attb_h);

    cudaFuncSetAttribute(gemm_h1,
                         cudaFuncAttributeMaxDynamicSharedMemorySize, GEMM_SMEM);
    cudaFuncSetAttribute(attn_mma,
                         cudaFuncAttributeMaxDynamicSharedMemorySize, AT_SMEM);

    // conversions
    conv_h<<<(NT_ * H_ / 4 + 255) / 256, 256>>>(
        (const float4*)hidden, (uint2*)hid_h, NT_ * H_ / 4);
    conv_hT<<<dim3(H_ / 32, H_ / 32), dim3(32, 8)>>>(wq, wqkv_h, H_, H_);
    conv_hT<<<dim3((HKV_ * D_) / 32, H_ / 32), dim3(32, 8)>>>(
        wk, wqkv_h + (size_t)H_ * H_, H_, HKV_ * D_);
    conv_hT<<<dim3((HKV_ * D_) / 32, H_ / 32), dim3(32, 8)>>>(
        wv, wqkv_h + (size_t)(H_ + HKV_ * D_) * H_, H_, HKV_ * D_);
    conv_hT<<<dim3(H_ / 32, H_ / 32), dim3(32, 8)>>>(wo, wo_h, H_, H_);

    // fused QKV projection
    gemm_h1<<<dim3(NQKV / 128, NT_ / 128), 256, GEMM_SMEM>>>(
        hid_h, wqkv_h,
        q, ktmp, vtmp, H_, H_ + HKV_ * D_, H_, HKV_ * D_, HKV_ * D_, H_);

    // rope + KV assembly
    rope_q_kernel<<<(NT_ * HQ_ * 64) / 256, 256>>>();
    rope_scatter_k_kernel<<<(NT_ * HKV_ * 64) / 256, 256>>>();
    scatter_v_kernel<<<(NT_ * HKV_ * D_ / 2) / 256, 256>>>();
    copy_cache_kernel<<<(B_ * L_ * HKV_ * D_ / 2) / 256, 256>>>(
        (const float2*)k_cache, (const float2*)v_cache);

    // attention
    attn_mma<<<dim3(S_ / 128, HQ_, B_), 256, AT_SMEM>>>();

    // output projection
    gemm_h1<<<dim3(H_ / 128, NT_ / 128), 256, GEMM_SMEM>>>(
        attb_h, wo_h,
        out, out, out, H_, H_, H_, H_, H_, H_);
}

// round 9
// speedup vs baseline: 1.9362x; 1.0990x over previous
#include <cuda_runtime.h>
#include <cuda_fp16.h>
#include <math.h>
#include <stdint.h>

// Problem constants
#define B_    8
#define S_    512
#define H_    4096
#define HQ_   32
#define HKV_  8
#define D_    128
#define L_    1536
#define T_    2048
#define NT_   (B_*S_)
#define THETA_ 500000.0f
#define NQKV  (H_ + 2*HKV_*D_)      // 6144
// -log2(THETA)/64
#define ROPE_C (-0.2958058953f)

// ---------------- scratch (device globals) ----------------------------------
__device__ float g_q   [(size_t)NT_*HQ_ *D_];
__device__ float g_ktmp[(size_t)NT_*HKV_*D_];
__device__ float g_vtmp[(size_t)NT_*HKV_*D_];

__device__ __half g_hid_h [(size_t)NT_*H_];
__device__ __half g_wqkvT_h[(size_t)NQKV*H_];
__device__ __half g_woT_h [(size_t)H_*H_];
__device__ __half g_attb_h[(size_t)NT_*H_];

__device__ __half g_qb_h[(size_t)NT_*HQ_*D_];
__device__ __half g_qb_l[(size_t)NT_*HQ_*D_];
__device__ __half g_kb_h[(size_t)B_*T_*HKV_*D_];
__device__ __half g_kb_l[(size_t)B_*T_*HKV_*D_];
__device__ __half g_vb_h[(size_t)B_*T_*HKV_*D_];
__device__ __half g_vb_l[(size_t)B_*T_*HKV_*D_];

// ---------------- helpers ----------------------------------------------------
__device__ __forceinline__ uint32_t smem_u32(const void* p) {
    uint32_t r;
    asm("{ .reg .u64 t; cvta.to.shared.u64 t, %1; cvt.u32.u64 %0, t; }"
        : "=r"(r) : "l"(p));
    return r;
}
__device__ __forceinline__ uint16_t h_hi(float x) {
    __half h = __float2half_rn(x);
    return *reinterpret_cast<uint16_t*>(&h);
}
__device__ __forceinline__ float h_back(uint16_t u) {
    __half h = *reinterpret_cast<__half*>(&u);
    return __half2float(h);
}
__device__ __forceinline__ uint32_t pack_h2(float lo, float hi) {
    __half2 h = __floats2half2_rn(lo, hi);       // lo -> low half
    return *reinterpret_cast<uint32_t*>(&h);
}
__device__ __forceinline__ float h2lo(uint32_t p) {
    __half2 h = *reinterpret_cast<__half2*>(&p);
    return __low2float(h);
}
__device__ __forceinline__ float h2hi(uint32_t p) {
    __half2 h = *reinterpret_cast<__half2*>(&p);
    return __high2float(h);
}

#define CP_ASYNC16(dst, src) \
    asm volatile("cp.async.cg.shared.global [%0], [%1], 16;" :: "r"(dst), "l"(src))
#define CP_COMMIT() asm volatile("cp.async.commit_group;")
#define CP_WAIT2()  asm volatile("cp.async.wait_group 2;")
#define CP_WAIT1()  asm volatile("cp.async.wait_group 1;")
#define CP_WAIT0()  asm volatile("cp.async.wait_group 0;")

#define LDSM4(r, a) \
    asm volatile("ldmatrix.sync.aligned.m8n8.x4.shared.b16 {%0,%1,%2,%3}, [%4];" \
                 : "=r"((r)[0]), "=r"((r)[1]), "=r"((r)[2]), "=r"((r)[3]) : "r"(a))
#define LDSM4T(r, a) \
    asm volatile("ldmatrix.sync.aligned.m8n8.x4.trans.shared.b16 {%0,%1,%2,%3}, [%4];" \
                 : "=r"((r)[0]), "=r"((r)[1]), "=r"((r)[2]), "=r"((r)[3]) : "r"(a))

#define MMA_F16(c, a, b0v, b1v) \
    asm volatile("mma.sync.aligned.m16n8k16.row.col.f32.f16.f16.f32 " \
                 "{%0,%1,%2,%3}, {%4,%5,%6,%7}, {%8,%9}, {%0,%1,%2,%3};" \
                 : "+f"((c)[0]), "+f"((c)[1]), "+f"((c)[2]), "+f"((c)[3]) \
                 : "r"((a)[0]), "r"((a)[1]), "r"((a)[2]), "r"((a)[3]), \
                   "r"(b0v), "r"(b1v))

// ---------------- fp32 -> fp16 (hi only) -------------------------------------
__global__ void conv_h(const float4* __restrict__ in, uint2* __restrict__ oh, int n4)
{
    int i = blockIdx.x * blockDim.x + threadIdx.x;
    if (i >= n4) return;
    float4 v = in[i];
    oh[i] = make_uint2(pack_h2(v.x, v.y), pack_h2(v.z, v.w));
}

// ---------------- fp32 [K][N] -> fp16 transposed [N][K] ----------------------
// 64(k) x 32(n) tile; packed uint32 stores (128B contiguous per n-row).
__global__ void conv_hT(const float* __restrict__ in,
                        __half* __restrict__ oh, int K, int N)
{
    __shared__ float t[64][33];
    const int n0 = blockIdx.x * 32;
    const int k0 = blockIdx.y * 64;
    const int x = threadIdx.x & 31;
    const int y = threadIdx.x >> 5;        // 0..7
#pragma unroll
    for (int it = 0; it < 8; it++) {
        int row = it * 8 + y;
        t[row][x] = in[(size_t)(k0 + row) * N + n0 + x];
    }
    __syncthreads();
    const int u  = threadIdx.x & 31;       // k-pair index
    const int nr = threadIdx.x >> 5;       // 0..7
    uint16_t* o16 = reinterpret_cast<uint16_t*>(oh);
#pragma unroll
    for (int it = 0; it < 4; it++) {
        int n = it * 8 + nr;
        uint32_t p = pack_h2(t[2 * u][n], t[2 * u + 1][n]);
        *reinterpret_cast<uint32_t*>(o16 + (size_t)(n0 + n) * K + k0 + 2 * u) = p;
    }
}

// ============================================================================
// fp16 1-term GEMM (unchanged from R8)
// ============================================================================
#define GSTAGE 16384
#define GEMM_SMEM (3 * GSTAGE)

__global__ __launch_bounds__(256) void gemm_h1(
    const __half* __restrict__ Ah, const __half* __restrict__ Bh,
    float* __restrict__ C0, float* __restrict__ C1, float* __restrict__ C2,
    int n0, int n1, int ld0, int ld1, int ld2, int K)
{
    extern __shared__ char smem[];
    const uint32_t sb = smem_u32(smem);
    const int tid  = threadIdx.x;
    const int lane = tid & 31;
    const int wid  = tid >> 5;
    const int bm   = blockIdx.y * 128;
    const int bn   = blockIdx.x * 128;
    const int wm   = (wid >> 2) * 64;
    const int wn   = (wid & 3) * 32;

    const int lrow = tid >> 2;
    const int lchk = tid & 3;
    const uint32_t dsw = (uint32_t)(lrow * 64 + ((lchk ^ ((lrow >> 1) & 3)) * 16));

    const int arow = ((lane >> 3) & 1) * 8 + (lane & 7);
    const int akc  = lane >> 4;
    const int aph  = ((lane & 7) >> 1) & 3;
    const uint32_t aBase = (uint32_t)((wm + arow) * 64);

    const int brow8 = lane & 7;
    const int bkc   = (lane >> 3) & 1;
    const int bj1   = (lane >> 4) & 1;
    const int bph   = (brow8 >> 1) & 3;
    const uint32_t bBase = (uint32_t)((wn + bj1 * 8 + brow8) * 64);

    float acc[4][4][4];
#pragma unroll
    for (int i = 0; i < 4; i++)
#pragma unroll
        for (int j = 0; j < 4; j++) {
            acc[i][j][0] = 0.f; acc[i][j][1] = 0.f;
            acc[i][j][2] = 0.f; acc[i][j][3] = 0.f;
        }

    const int nk = K / 32;

    auto issue = [&](int st, int k0) {
        const uint32_t s = sb + st * GSTAGE;
        {
            const __half* g = Ah + (size_t)(bm + lrow) * K + k0 + lchk * 8;
            uint32_t d = s + dsw;
            CP_ASYNC16(d, g);
            CP_ASYNC16(d + 4096, g + (size_t)64 * K);
        }
        {
            const __half* g = Bh + (size_t)(bn + lrow) * K + k0 + lchk * 8;
            uint32_t d = s + 8192 + dsw;
            CP_ASYNC16(d, g);
            CP_ASYNC16(d + 4096, g + (size_t)64 * K);
        }
        CP_COMMIT();
    };

    issue(0, 0);
    issue(1, 32);
    issue(2, 64);

    int st = 0;
    for (int ck = 0; ck < nk; ck++) {
        const int rem = nk - 1 - ck;
        if (rem >= 2) { CP_WAIT2(); } else if (rem == 1) { CP_WAIT1(); } else { CP_WAIT0(); }
        __syncthreads();

        const uint32_t s   = sb + st * GSTAGE;
        const uint32_t sA  = s + aBase;
        const uint32_t sBH = s + 8192 + bBase;

#pragma unroll
        for (int ks = 0; ks < 2; ks++) {
            const uint32_t cA = (uint32_t)(((ks * 2 + akc) ^ aph) * 16);
            const uint32_t cB = (uint32_t)(((ks * 2 + bkc) ^ bph) * 16);

            uint32_t aF[4][4];
#pragma unroll
            for (int i = 0; i < 4; i++) LDSM4(aF[i], sA + i * 1024 + cA);

            uint32_t bH[4][2];
#pragma unroll
            for (int jp = 0; jp < 2; jp++) {
                uint32_t r4[4];
                LDSM4(r4, sBH + jp * 1024 + cB);
                bH[2*jp][0] = r4[0]; bH[2*jp][1] = r4[1];
                bH[2*jp+1][0] = r4[2]; bH[2*jp+1][1] = r4[3];
            }

#pragma unroll
            for (int i = 0; i < 4; i++)
#pragma unroll
                for (int j = 0; j < 4; j++)
                    MMA_F16(acc[i][j], aF[i], bH[j][0], bH[j][1]);
        }
        __syncthreads();
        if (ck + 3 < nk) issue(st, (ck + 3) * 32);
        st = (st == 2) ? 0 : st + 1;
    }

    float* Cp;
    int ld, cbase;
    if (bn < n0)      { Cp = C0; ld = ld0; cbase = bn; }
    else if (bn < n1) { Cp = C1; ld = ld1; cbase = bn - n0; }
    else              { Cp = C2; ld = ld2; cbase = bn - n1; }

    const int g4 = lane >> 2, t4 = lane & 3;
#pragma unroll
    for (int i = 0; i < 4; i++) {
        const int row = bm + wm + i * 16 + g4;
#pragma unroll
        for (int j = 0; j < 4; j++) {
            const int col = cbase + wn + j * 8 + t4 * 2;
            *reinterpret_cast<float2*>(&Cp[(size_t)row * ld + col]) =
                make_float2(acc[i][j][0], acc[i][j][1]);
            *reinterpret_cast<float2*>(&Cp[(size_t)(row + 8) * ld + col]) =
                make_float2(acc[i][j][2], acc[i][j][3]);
        }
    }
}

// ---------------- RoPE Q -> fp16 split (wide: 4 d-pairs/thread) --------------
__global__ void rope_q_kernel()
{
    int idx = blockIdx.x * blockDim.x + threadIdx.x;
    if (idx >= NT_ * HQ_ * 16) return;
    int j   = (idx & 15) * 4;
    int th  = idx >> 4;
    int tok = th >> 5;
    int s   = tok & (S_ - 1);
    float pos = (float)(L_ + s);
    size_t o = (size_t)th * D_;
    float4 a = *reinterpret_cast<const float4*>(g_q + o + j);
    float4 b = *reinterpret_cast<const float4*>(g_q + o + 64 + j);
    float x1[4] = {a.x, a.y, a.z, a.w};
    float x2[4] = {b.x, b.y, b.z, b.w};
    float y1[4], y2[4];
#pragma unroll
    for (int i = 0; i < 4; i++) {
        float ang = pos * exp2f((float)(j + i) * ROPE_C);
        float c, sn;
        sincosf(ang, &sn, &c);
        y1[i] = x1[i] * c - x2[i] * sn;
        y2[i] = x2[i] * c + x1[i] * sn;
    }
    uint32_t h1a = pack_h2(y1[0], y1[1]), h1b = pack_h2(y1[2], y1[3]);
    uint32_t h2a = pack_h2(y2[0], y2[1]), h2b = pack_h2(y2[2], y2[3]);
    uint32_t l1a = pack_h2(y1[0] - h2lo(h1a), y1[1] - h2hi(h1a));
    uint32_t l1b = pack_h2(y1[2] - h2lo(h1b), y1[3] - h2hi(h1b));
    uint32_t l2a = pack_h2(y2[0] - h2lo(h2a), y2[1] - h2hi(h2a));
    uint32_t l2b = pack_h2(y2[2] - h2lo(h2b), y2[3] - h2hi(h2b));
    uint16_t* qh = reinterpret_cast<uint16_t*>(g_qb_h);
    uint16_t* ql = reinterpret_cast<uint16_t*>(g_qb_l);
    *reinterpret_cast<uint2*>(qh + o + j)      = make_uint2(h1a, h1b);
    *reinterpret_cast<uint2*>(qh + o + 64 + j) = make_uint2(h2a, h2b);
    *reinterpret_cast<uint2*>(ql + o + j)      = make_uint2(l1a, l1b);
    *reinterpret_cast<uint2*>(ql + o + 64 + j) = make_uint2(l2a, l2b);
}

// ---------------- RoPE new K -> fp16 split scatter (wide) --------------------
__global__ void rope_scatter_k_kernel()
{
    int idx = blockIdx.x * blockDim.x + threadIdx.x;
    if (idx >= NT_ * HKV_ * 16) return;
    int j   = (idx & 15) * 4;
    int th  = idx >> 4;
    int tok = th >> 3;
    int kvh = th & 7;
    int b   = tok >> 9;
    int s   = tok & 511;
    float pos = (float)(L_ + s);
    const float* src = g_ktmp + (size_t)th * D_;
    float4 a = *reinterpret_cast<const float4*>(src + j);
    float4 c4 = *reinterpret_cast<const float4*>(src + 64 + j);
    float x1[4] = {a.x, a.y, a.z, a.w};
    float x2[4] = {c4.x, c4.y, c4.z, c4.w};
    float y1[4], y2[4];
#pragma unroll
    for (int i = 0; i < 4; i++) {
        float ang = pos * exp2f((float)(j + i) * ROPE_C);
        float c, sn;
        sincosf(ang, &sn, &c);
        y1[i] = x1[i] * c - x2[i] * sn;
        y2[i] = x2[i] * c + x1[i] * sn;
    }
    size_t o = (((size_t)(b * T_ + L_ + s)) * HKV_ + kvh) * D_;
    uint32_t h1a = pack_h2(y1[0], y1[1]), h1b = pack_h2(y1[2], y1[3]);
    uint32_t h2a = pack_h2(y2[0], y2[1]), h2b = pack_h2(y2[2], y2[3]);
    uint32_t l1a = pack_h2(y1[0] - h2lo(h1a), y1[1] - h2hi(h1a));
    uint32_t l1b = pack_h2(y1[2] - h2lo(h1b), y1[3] - h2hi(h1b));
    uint32_t l2a = pack_h2(y2[0] - h2lo(h2a), y2[1] - h2hi(h2a));
    uint32_t l2b = pack_h2(y2[2] - h2lo(h2b), y2[3] - h2hi(h2b));
    uint16_t* kh = reinterpret_cast<uint16_t*>(g_kb_h);
    uint16_t* kl = reinterpret_cast<uint16_t*>(g_kb_l);
    *reinterpret_cast<uint2*>(kh + o + j)      = make_uint2(h1a, h1b);
    *reinterpret_cast<uint2*>(kh + o + 64 + j) = make_uint2(h2a, h2b);
    *reinterpret_cast<uint2*>(kl + o + j)      = make_uint2(l1a, l1b);
    *reinterpret_cast<uint2*>(kl + o + 64 + j) = make_uint2(l2a, l2b);
}

// ---------------- new V -> fp16 split scatter (float4 granule) ---------------
__global__ void scatter_v_kernel()
{
    int idx = blockIdx.x * blockDim.x + threadIdx.x;
    const int n = NT_ * HKV_ * D_ / 4;
    if (idx >= n) return;
    int e   = idx * 4;
    int tok = e >> 10;
    int r   = e & 1023;
    int b   = tok >> 9;
    int s   = tok & 511;
    float4 v = reinterpret_cast<const float4*>(g_vtmp)[idx];
    uint32_t ha = pack_h2(v.x, v.y), hb = pack_h2(v.z, v.w);
    uint32_t la = pack_h2(v.x - h2lo(ha), v.y - h2hi(ha));
    uint32_t lb = pack_h2(v.z - h2lo(hb), v.w - h2hi(hb));
    size_t o = (((size_t)(b * T_ + L_ + s)) * HKV_) * D_ + r;
    *reinterpret_cast<uint2*>(reinterpret_cast<uint16_t*>(g_vb_h) + o) = make_uint2(ha, hb);
    *reinterpret_cast<uint2*>(reinterpret_cast<uint16_t*>(g_vb_l) + o) = make_uint2(la, lb);
}

// ---------------- cache -> fp16 split (float4 granule) -----------------------
__global__ void copy_cache_kernel(const float4* __restrict__ kc,
                                  const float4* __restrict__ vc)
{
    int idx = blockIdx.x * blockDim.x + threadIdx.x;
    const int n = B_ * L_ * HKV_ * D_ / 4;
    if (idx >= n) return;
    const int perb4 = L_ * HKV_ * D_ / 4;
    int b = idx / perb4;
    size_t o = ((size_t)idx + (size_t)b * ((T_ - L_) * HKV_ * D_ / 4)) * 4;
    float4 k = kc[idx];
    float4 v = vc[idx];
    uint32_t kha = pack_h2(k.x, k.y), khb = pack_h2(k.z, k.w);
    uint32_t kla = pack_h2(k.x - h2lo(kha), k.y - h2hi(kha));
    uint32_t klb = pack_h2(k.z - h2lo(khb), k.w - h2hi(khb));
    uint32_t vha = pack_h2(v.x, v.y), vhb = pack_h2(v.z, v.w);
    uint32_t vla = pack_h2(v.x - h2lo(vha), v.y - h2hi(vha));
    uint32_t vlb = pack_h2(v.z - h2lo(vhb), v.w - h2hi(vhb));
    *reinterpret_cast<uint2*>(reinterpret_cast<uint16_t*>(g_kb_h) + o) = make_uint2(kha, khb);
    *reinterpret_cast<uint2*>(reinterpret_cast<uint16_t*>(g_kb_l) + o) = make_uint2(kla, klb);
    *reinterpret_cast<uint2*>(reinterpret_cast<uint16_t*>(g_vb_h) + o) = make_uint2(vha, vhb);
    *reinterpret_cast<uint2*>(reinterpret_cast<uint16_t*>(g_vb_l) + o) = make_uint2(vla, vlb);
}

// ============================================================================
// Tensor-core flash attention: QK 3-term, PV 2-term (Pl dropped)
// ============================================================================
#define AT_STAGE 65536
#define AT_SMEM  (2 * AT_STAGE)
#define SC_LOG2E 0.12751884817f

__global__ __launch_bounds__(256, 1) void attn_mma()
{
    extern __shared__ char smem[];
    const uint32_t sb = smem_u32(smem);
    const int tid  = threadIdx.x;
    const int lane = tid & 31;
    const int w    = tid >> 5;
    const int g    = lane >> 2;
    const int t4   = lane & 3;
    const int qt   = blockIdx.x;
    const int hq   = blockIdx.y;
    const int b    = blockIdx.z;
    const int kvh  = hq >> 2;

    {
        const int qr  = tid >> 1;
        const int qcb = (tid & 1) * 8;
        const size_t qo = ((size_t)(b * S_ + qt * 128 + qr)) * (HQ_ * D_) + hq * D_;
#pragma unroll
        for (int i = 0; i < 8; i++) {
            int ch = qcb + i;
            uint32_t d = sb + qr * 256 + ((ch ^ (qr & 7)) * 16);
            CP_ASYNC16(d,         g_qb_h + qo + ch * 8);
            CP_ASYNC16(d + 32768, g_qb_l + qo + ch * 8);
        }
        CP_COMMIT();
        CP_WAIT0();
    }
    __syncthreads();

    uint32_t qh[8][4], ql[8][4];
    {
        const int tt  = lane >> 3;
        const int qrow = 16 * w + (tt & 1) * 8 + (lane & 7);
        const int chi  = tt >> 1;
#pragma unroll
        for (int kk = 0; kk < 8; kk++) {
            uint32_t a = sb + qrow * 256 + (((2 * kk + chi) ^ (qrow & 7)) * 16);
            LDSM4(qh[kk], a);
            LDSM4(ql[kk], a + 32768);
        }
    }
    __syncthreads();

    const int ntiles = 26 + 2 * qt;
    const int mask_from = 24 + 2 * qt;

    auto issueKV = [&](int stage, int kt) {
        const uint32_t s = sb + stage * AT_STAGE;
        const int trow = tid >> 2;
        const int cb   = (tid & 3) * 4;
        const size_t go = (((size_t)(b * T_ + kt * 64 + trow)) * HKV_ + kvh) * D_;
        const uint32_t rb = s + trow * 256;
#pragma unroll
        for (int i = 0; i < 4; i++) {
            int ch = cb + i;
            uint32_t d = rb + ((ch ^ (trow & 7)) * 16);
            CP_ASYNC16(d,         g_kb_h + go + ch * 8);
            CP_ASYNC16(d + 16384, g_kb_l + go + ch * 8);
            CP_ASYNC16(d + 32768, g_vb_h + go + ch * 8);
            CP_ASYNC16(d + 49152, g_vb_l + go + ch * 8);
        }
        CP_COMMIT();
    };

    issueKV(0, 0);
    issueKV(1, 1);

    float oacc[16][4];
#pragma unroll
    for (int j = 0; j < 16; j++) {
        oacc[j][0] = 0.f; oacc[j][1] = 0.f; oacc[j][2] = 0.f; oacc[j][3] = 0.f;
    }
    float m0 = -1e30f, m1 = -1e30f, l0 = 0.f, l1 = 0.f;

    const int tt   = lane >> 3;
    const int krb  = (tt >> 1) * 8 + (lane & 7);
    const int kch1 = tt & 1;
    const int vrb  = (tt & 1) * 8 + (lane & 7);
    const int vch1 = tt >> 1;

    for (int kt = 0; kt < ntiles; kt++) {
        if (kt + 1 < ntiles) { CP_WAIT1(); } else { CP_WAIT0(); }
        __syncthreads();

        const uint32_t s = sb + (kt & 1) * AT_STAGE;

        float sacc[8][4];
#pragma unroll
        for (int j = 0; j < 8; j++) {
            sacc[j][0] = 0.f; sacc[j][1] = 0.f; sacc[j][2] = 0.f; sacc[j][3] = 0.f;
        }
#pragma unroll
        for (int kk = 0; kk < 8; kk++) {
#pragma unroll
            for (int jp = 0; jp < 4; jp++) {
                const int trow = jp * 16 + krb;
                const uint32_t addr = s + trow * 256 +
                                      (((2 * kk + kch1) ^ (trow & 7)) * 16);
                uint32_t bh[4], bl[4];
                LDSM4(bh, addr);
                LDSM4(bl, addr + 16384);
                MMA_F16(sacc[2*jp],   qh[kk], bh[0], bh[1]);
                MMA_F16(sacc[2*jp+1], qh[kk], bh[2], bh[3]);
                MMA_F16(sacc[2*jp],   qh[kk], bl[0], bl[1]);
                MMA_F16(sacc[2*jp+1], qh[kk], bl[2], bl[3]);
                MMA_F16(sacc[2*jp],   ql[kk], bh[0], bh[1]);
                MMA_F16(sacc[2*jp+1], ql[kk], bh[2], bh[3]);
            }
        }

        if (kt >= mask_from) {
            const int colb = kt * 64 + 2 * t4;
            const int alw0 = L_ + qt * 128 + 16 * w + g;
            const int alw1 = alw0 + 8;
#pragma unroll
            for (int j = 0; j < 8; j++) {
                int c0 = colb + j * 8;
                if (c0 > alw0)     sacc[j][0] = -1e30f;
                if (c0 + 1 > alw0) sacc[j][1] = -1e30f;
                if (c0 > alw1)     sacc[j][2] = -1e30f;
                if (c0 + 1 > alw1) sacc[j][3] = -1e30f;
            }
        }

        float rm0 = -1e30f, rm1 = -1e30f;
#pragma unroll
        for (int j = 0; j < 8; j++) {
            rm0 = fmaxf(rm0, fmaxf(sacc[j][0], sacc[j][1]));
            rm1 = fmaxf(rm1, fmaxf(sacc[j][2], sacc[j][3]));
        }
        rm0 = fmaxf(rm0, __shfl_xor_sync(0xFFFFFFFFu, rm0, 1));
        rm0 = fmaxf(rm0, __shfl_xor_sync(0xFFFFFFFFu, rm0, 2));
        rm1 = fmaxf(rm1, __shfl_xor_sync(0xFFFFFFFFu, rm1, 1));
        rm1 = fmaxf(rm1, __shfl_xor_sync(0xFFFFFFFFu, rm1, 2));

        const float nm0 = fmaxf(m0, rm0), nm1 = fmaxf(m1, rm1);
        const float f0 = exp2f((m0 - nm0) * SC_LOG2E);
        const float f1 = exp2f((m1 - nm1) * SC_LOG2E);
        float rs0 = 0.f, rs1 = 0.f;
#pragma unroll
        for (int j = 0; j < 8; j++) {
            sacc[j][0] = exp2f((sacc[j][0] - nm0) * SC_LOG2E);
            sacc[j][1] = exp2f((sacc[j][1] - nm0) * SC_LOG2E);
            sacc[j][2] = exp2f((sacc[j][2] - nm1) * SC_LOG2E);
            sacc[j][3] = exp2f((sacc[j][3] - nm1) * SC_LOG2E);
            rs0 += sacc[j][0] + sacc[j][1];
            rs1 += sacc[j][2] + sacc[j][3];
        }
        rs0 += __shfl_xor_sync(0xFFFFFFFFu, rs0, 1);
        rs0 += __shfl_xor_sync(0xFFFFFFFFu, rs0, 2);
        rs1 += __shfl_xor_sync(0xFFFFFFFFu, rs1, 1);
        rs1 += __shfl_xor_sync(0xFFFFFFFFu, rs1, 2);
        l0 = l0 * f0 + rs0;
        l1 = l1 * f1 + rs1;
        m0 = nm0; m1 = nm1;

#pragma unroll
        for (int j = 0; j < 16; j++) {
            oacc[j][0] *= f0; oacc[j][1] *= f0;
            oacc[j][2] *= f1; oacc[j][3] *= f1;
        }

        // P fragments: hi only (PV 2-term: Ph*Vh + Ph*Vl)
        uint32_t ph[4][4];
#pragma unroll
        for (int kc = 0; kc < 4; kc++) {
            ph[kc][0] = pack_h2(sacc[2*kc][0],   sacc[2*kc][1]);
            ph[kc][1] = pack_h2(sacc[2*kc][2],   sacc[2*kc][3]);
            ph[kc][2] = pack_h2(sacc[2*kc+1][0], sacc[2*kc+1][1]);
            ph[kc][3] = pack_h2(sacc[2*kc+1][2], sacc[2*kc+1][3]);
        }

        const uint32_t vbase = s + 32768;
#pragma unroll
        for (int jp2 = 0; jp2 < 8; jp2++) {
#pragma unroll
            for (int kc = 0; kc < 4; kc++) {
                const int trow = kc * 16 + vrb;
                const uint32_t addr = vbase + trow * 256 +
                                      (((jp2 * 2 + vch1) ^ (trow & 7)) * 16);
                uint32_t vh[4], vl[4];
                LDSM4T(vh, addr);
                LDSM4T(vl, addr + 16384);
                MMA_F16(oacc[2*jp2],   ph[kc], vh[0], vh[1]);
                MMA_F16(oacc[2*jp2+1], ph[kc], vh[2], vh[3]);
                MMA_F16(oacc[2*jp2],   ph[kc], vl[0], vl[1]);
                MMA_F16(oacc[2*jp2+1], ph[kc], vl[2], vl[3]);
            }
        }

        __syncthreads();
        if (kt + 2 < ntiles) issueKV(kt & 1, kt + 2);
    }

    const float il0 = 1.0f / l0;
    const float il1 = 1.0f / l1;
    const size_t tok0 = (size_t)(b * S_ + qt * 128 + 16 * w + g);
    uint32_t* oh32 = reinterpret_cast<uint32_t*>(g_attb_h);
#pragma unroll
    for (int jn = 0; jn < 16; jn++) {
        float o0 = oacc[jn][0] * il0, o1 = oacc[jn][1] * il0;
        float o2 = oacc[jn][2] * il1, o3 = oacc[jn][3] * il1;
        const size_t a0 = (tok0 * (HQ_ * D_) + hq * D_ + jn * 8 + 2 * t4) >> 1;
        const size_t a1 = a0 + (8 * (HQ_ * D_) >> 1);
        oh32[a0] = pack_h2(o0, o1);
        oh32[a1] = pack_h2(o2, o3);
    }
}

// ---------------- launcher ---------------------------------------------------
extern "C" void kernel_launch(void* const* d_in, const int* in_sizes, int n_in,
                              void* d_out, int out_size)
{
    const float* hidden  = (const float*)d_in[0];
    const float* k_cache = (const float*)d_in[1];
    const float* v_cache = (const float*)d_in[2];
    const float* wq      = (const float*)d_in[3];
    const float* wk      = (const float*)d_in[4];
    const float* wv      = (const float*)d_in[5];
    const float* wo      = (const float*)d_in[6];
    float* out = (float*)d_out;

    float *q, *ktmp, *vtmp;
    cudaGetSymbolAddress((void**)&q,    g_q);
    cudaGetSymbolAddress((void**)&ktmp, g_ktmp);
    cudaGetSymbolAddress((void**)&vtmp, g_vtmp);

    __half *hid_h, *wqkv_h, *wo_h, *attb_h;
    cudaGetSymbolAddress((void**)&hid_h,  g_hid_h);
    cudaGetSymbolAddress((void**)&wqkv_h, g_wqkvT_h);
    cudaGetSymbolAddress((void**)&wo_h,   g_woT_h);
    cudaGetSymbolAddress((void**)&attb_h, g_attb_h);

    cudaFuncSetAttribute(gemm_h1,
                         cudaFuncAttributeMaxDynamicSharedMemorySize, GEMM_SMEM);
    cudaFuncSetAttribute(attn_mma,
                         cudaFuncAttributeMaxDynamicSharedMemorySize, AT_SMEM);

    // conversions
    conv_h<<<(NT_ * H_ / 4 + 255) / 256, 256>>>(
        (const float4*)hidden, (uint2*)hid_h, NT_ * H_ / 4);
    conv_hT<<<dim3(H_ / 32, H_ / 64), 256>>>(wq, wqkv_h, H_, H_);
    conv_hT<<<dim3((HKV_ * D_) / 32, H_ / 64), 256>>>(
        wk, wqkv_h + (size_t)H_ * H_, H_, HKV_ * D_);
    conv_hT<<<dim3((HKV_ * D_) / 32, H_ / 64), 256>>>(
        wv, wqkv_h + (size_t)(H_ + HKV_ * D_) * H_, H_, HKV_ * D_);
    conv_hT<<<dim3(H_ / 32, H_ / 64), 256>>>(wo, wo_h, H_, H_);

    // fused QKV projection
    gemm_h1<<<dim3(NQKV / 128, NT_ / 128), 256, GEMM_SMEM>>>(
        hid_h, wqkv_h,
        q, ktmp, vtmp, H_, H_ + HKV_ * D_, H_, HKV_ * D_, HKV_ * D_, H_);

    // rope + KV assembly (wide granules)
    rope_q_kernel<<<(NT_ * HQ_ * 16) / 256, 256>>>();
    rope_scatter_k_kernel<<<(NT_ * HKV_ * 16) / 256, 256>>>();
    scatter_v_kernel<<<(NT_ * HKV_ * D_ / 4) / 256, 256>>>();
    copy_cache_kernel<<<(B_ * L_ * HKV_ * D_ / 4) / 256, 256>>>(
        (const float4*)k_cache, (const float4*)v_cache);

    // attention
    attn_mma<<<dim3(S_ / 128, HQ_, B_), 256, AT_SMEM>>>();

    // output projection
    gemm_h1<<<dim3(H_ / 128, NT_ / 128), 256, GEMM_SMEM>>>(
        attb_h, wo_h,
        out, out, out, H_, H_, H_, H_, H_, H_);
}

// round 10
// speedup vs baseline: 2.3503x; 1.2139x over previous
#include <cuda_runtime.h>
#include <cuda_fp16.h>
#include <math.h>
#include <stdint.h>

// Problem constants
#define B_    8
#define S_    512
#define H_    4096
#define HQ_   32
#define HKV_  8
#define D_    128
#define L_    1536
#define T_    2048
#define NT_   (B_*S_)
#define THETA_ 500000.0f
#define NQKV  (H_ + 2*HKV_*D_)      // 6144
// -log2(THETA)/64
#define ROPE_C (-0.2958058953f)

// ---------------- scratch (device globals) ----------------------------------
__device__ float g_q   [(size_t)NT_*HQ_ *D_];
__device__ float g_ktmp[(size_t)NT_*HKV_*D_];
__device__ float g_vtmp[(size_t)NT_*HKV_*D_];

__device__ __half g_hid_h [(size_t)NT_*H_];
__device__ __half g_wqkvT_h[(size_t)NQKV*H_];
__device__ __half g_woT_h [(size_t)H_*H_];
__device__ __half g_attb_h[(size_t)NT_*H_];

__device__ __half g_qb_h[(size_t)NT_*HQ_*D_];
__device__ __half g_qb_l[(size_t)NT_*HQ_*D_];
__device__ __half g_kb_h[(size_t)B_*T_*HKV_*D_];
__device__ __half g_vb_h[(size_t)B_*T_*HKV_*D_];

// ---------------- helpers ----------------------------------------------------
__device__ __forceinline__ uint32_t smem_u32(const void* p) {
    uint32_t r;
    asm("{ .reg .u64 t; cvta.to.shared.u64 t, %1; cvt.u32.u64 %0, t; }"
        : "=r"(r) : "l"(p));
    return r;
}
__device__ __forceinline__ uint32_t pack_h2(float lo, float hi) {
    __half2 h = __floats2half2_rn(lo, hi);       // lo -> low half
    return *reinterpret_cast<uint32_t*>(&h);
}
__device__ __forceinline__ float h2lo(uint32_t p) {
    __half2 h = *reinterpret_cast<__half2*>(&p);
    return __low2float(h);
}
__device__ __forceinline__ float h2hi(uint32_t p) {
    __half2 h = *reinterpret_cast<__half2*>(&p);
    return __high2float(h);
}

#define CP_ASYNC16(dst, src) \
    asm volatile("cp.async.cg.shared.global [%0], [%1], 16;" :: "r"(dst), "l"(src))
#define CP_COMMIT() asm volatile("cp.async.commit_group;")
#define CP_WAIT2()  asm volatile("cp.async.wait_group 2;")
#define CP_WAIT1()  asm volatile("cp.async.wait_group 1;")
#define CP_WAIT0()  asm volatile("cp.async.wait_group 0;")

#define LDSM4(r, a) \
    asm volatile("ldmatrix.sync.aligned.m8n8.x4.shared.b16 {%0,%1,%2,%3}, [%4];" \
                 : "=r"((r)[0]), "=r"((r)[1]), "=r"((r)[2]), "=r"((r)[3]) : "r"(a))
#define LDSM4T(r, a) \
    asm volatile("ldmatrix.sync.aligned.m8n8.x4.trans.shared.b16 {%0,%1,%2,%3}, [%4];" \
                 : "=r"((r)[0]), "=r"((r)[1]), "=r"((r)[2]), "=r"((r)[3]) : "r"(a))

#define MMA_F16(c, a, b0v, b1v) \
    asm volatile("mma.sync.aligned.m16n8k16.row.col.f32.f16.f16.f32 " \
                 "{%0,%1,%2,%3}, {%4,%5,%6,%7}, {%8,%9}, {%0,%1,%2,%3};" \
                 : "+f"((c)[0]), "+f"((c)[1]), "+f"((c)[2]), "+f"((c)[3]) \
                 : "r"((a)[0]), "r"((a)[1]), "r"((a)[2]), "r"((a)[3]), \
                   "r"(b0v), "r"(b1v))

// ---------------- fp32 -> fp16 (hi only) -------------------------------------
__global__ void conv_h(const float4* __restrict__ in, uint2* __restrict__ oh, int n4)
{
    int i = blockIdx.x * blockDim.x + threadIdx.x;
    if (i >= n4) return;
    float4 v = in[i];
    oh[i] = make_uint2(pack_h2(v.x, v.y), pack_h2(v.z, v.w));
}

// ---------------- fp32 [K][N] -> fp16 transposed [N][K] ----------------------
__global__ void conv_hT(const float* __restrict__ in,
                        __half* __restrict__ oh, int K, int N)
{
    __shared__ float t[64][33];
    const int n0 = blockIdx.x * 32;
    const int k0 = blockIdx.y * 64;
    const int x = threadIdx.x & 31;
    const int y = threadIdx.x >> 5;        // 0..7
#pragma unroll
    for (int it = 0; it < 8; it++) {
        int row = it * 8 + y;
        t[row][x] = in[(size_t)(k0 + row) * N + n0 + x];
    }
    __syncthreads();
    const int u  = threadIdx.x & 31;       // k-pair index
    const int nr = threadIdx.x >> 5;       // 0..7
    uint16_t* o16 = reinterpret_cast<uint16_t*>(oh);
#pragma unroll
    for (int it = 0; it < 4; it++) {
        int n = it * 8 + nr;
        uint32_t p = pack_h2(t[2 * u][n], t[2 * u + 1][n]);
        *reinterpret_cast<uint32_t*>(o16 + (size_t)(n0 + n) * K + k0 + 2 * u) = p;
    }
}

// ============================================================================
// fp16 1-term GEMM (unchanged from R8/R9)
// ============================================================================
#define GSTAGE 16384
#define GEMM_SMEM (3 * GSTAGE)

__global__ __launch_bounds__(256) void gemm_h1(
    const __half* __restrict__ Ah, const __half* __restrict__ Bh,
    float* __restrict__ C0, float* __restrict__ C1, float* __restrict__ C2,
    int n0, int n1, int ld0, int ld1, int ld2, int K)
{
    extern __shared__ char smem[];
    const uint32_t sb = smem_u32(smem);
    const int tid  = threadIdx.x;
    const int lane = tid & 31;
    const int wid  = tid >> 5;
    const int bm   = blockIdx.y * 128;
    const int bn   = blockIdx.x * 128;
    const int wm   = (wid >> 2) * 64;
    const int wn   = (wid & 3) * 32;

    const int lrow = tid >> 2;
    const int lchk = tid & 3;
    const uint32_t dsw = (uint32_t)(lrow * 64 + ((lchk ^ ((lrow >> 1) & 3)) * 16));

    const int arow = ((lane >> 3) & 1) * 8 + (lane & 7);
    const int akc  = lane >> 4;
    const int aph  = ((lane & 7) >> 1) & 3;
    const uint32_t aBase = (uint32_t)((wm + arow) * 64);

    const int brow8 = lane & 7;
    const int bkc   = (lane >> 3) & 1;
    const int bj1   = (lane >> 4) & 1;
    const int bph   = (brow8 >> 1) & 3;
    const uint32_t bBase = (uint32_t)((wn + bj1 * 8 + brow8) * 64);

    float acc[4][4][4];
#pragma unroll
    for (int i = 0; i < 4; i++)
#pragma unroll
        for (int j = 0; j < 4; j++) {
            acc[i][j][0] = 0.f; acc[i][j][1] = 0.f;
            acc[i][j][2] = 0.f; acc[i][j][3] = 0.f;
        }

    const int nk = K / 32;

    auto issue = [&](int st, int k0) {
        const uint32_t s = sb + st * GSTAGE;
        {
            const __half* g = Ah + (size_t)(bm + lrow) * K + k0 + lchk * 8;
            uint32_t d = s + dsw;
            CP_ASYNC16(d, g);
            CP_ASYNC16(d + 4096, g + (size_t)64 * K);
        }
        {
            const __half* g = Bh + (size_t)(bn + lrow) * K + k0 + lchk * 8;
            uint32_t d = s + 8192 + dsw;
            CP_ASYNC16(d, g);
            CP_ASYNC16(d + 4096, g + (size_t)64 * K);
        }
        CP_COMMIT();
    };

    issue(0, 0);
    issue(1, 32);
    issue(2, 64);

    int st = 0;
    for (int ck = 0; ck < nk; ck++) {
        const int rem = nk - 1 - ck;
        if (rem >= 2) { CP_WAIT2(); } else if (rem == 1) { CP_WAIT1(); } else { CP_WAIT0(); }
        __syncthreads();

        const uint32_t s   = sb + st * GSTAGE;
        const uint32_t sA  = s + aBase;
        const uint32_t sBH = s + 8192 + bBase;

#pragma unroll
        for (int ks = 0; ks < 2; ks++) {
            const uint32_t cA = (uint32_t)(((ks * 2 + akc) ^ aph) * 16);
            const uint32_t cB = (uint32_t)(((ks * 2 + bkc) ^ bph) * 16);

            uint32_t aF[4][4];
#pragma unroll
            for (int i = 0; i < 4; i++) LDSM4(aF[i], sA + i * 1024 + cA);

            uint32_t bH[4][2];
#pragma unroll
            for (int jp = 0; jp < 2; jp++) {
                uint32_t r4[4];
                LDSM4(r4, sBH + jp * 1024 + cB);
                bH[2*jp][0] = r4[0]; bH[2*jp][1] = r4[1];
                bH[2*jp+1][0] = r4[2]; bH[2*jp+1][1] = r4[3];
            }

#pragma unroll
            for (int i = 0; i < 4; i++)
#pragma unroll
                for (int j = 0; j < 4; j++)
                    MMA_F16(acc[i][j], aF[i], bH[j][0], bH[j][1]);
        }
        __syncthreads();
        if (ck + 3 < nk) issue(st, (ck + 3) * 32);
        st = (st == 2) ? 0 : st + 1;
    }

    float* Cp;
    int ld, cbase;
    if (bn < n0)      { Cp = C0; ld = ld0; cbase = bn; }
    else if (bn < n1) { Cp = C1; ld = ld1; cbase = bn - n0; }
    else              { Cp = C2; ld = ld2; cbase = bn - n1; }

    const int g4 = lane >> 2, t4 = lane & 3;
#pragma unroll
    for (int i = 0; i < 4; i++) {
        const int row = bm + wm + i * 16 + g4;
#pragma unroll
        for (int j = 0; j < 4; j++) {
            const int col = cbase + wn + j * 8 + t4 * 2;
            *reinterpret_cast<float2*>(&Cp[(size_t)row * ld + col]) =
                make_float2(acc[i][j][0], acc[i][j][1]);
            *reinterpret_cast<float2*>(&Cp[(size_t)(row + 8) * ld + col]) =
                make_float2(acc[i][j][2], acc[i][j][3]);
        }
    }
}

// ---------------- RoPE Q -> fp16 split (Q keeps hi+lo) -----------------------
__global__ void rope_q_kernel()
{
    int idx = blockIdx.x * blockDim.x + threadIdx.x;
    if (idx >= NT_ * HQ_ * 16) return;
    int j   = (idx & 15) * 4;
    int th  = idx >> 4;
    int tok = th >> 5;
    int s   = tok & (S_ - 1);
    float pos = (float)(L_ + s);
    size_t o = (size_t)th * D_;
    float4 a = *reinterpret_cast<const float4*>(g_q + o + j);
    float4 b = *reinterpret_cast<const float4*>(g_q + o + 64 + j);
    float x1[4] = {a.x, a.y, a.z, a.w};
    float x2[4] = {b.x, b.y, b.z, b.w};
    float y1[4], y2[4];
#pragma unroll
    for (int i = 0; i < 4; i++) {
        float ang = pos * exp2f((float)(j + i) * ROPE_C);
        float c, sn;
        sincosf(ang, &sn, &c);
        y1[i] = x1[i] * c - x2[i] * sn;
        y2[i] = x2[i] * c + x1[i] * sn;
    }
    uint32_t h1a = pack_h2(y1[0], y1[1]), h1b = pack_h2(y1[2], y1[3]);
    uint32_t h2a = pack_h2(y2[0], y2[1]), h2b = pack_h2(y2[2], y2[3]);
    uint32_t l1a = pack_h2(y1[0] - h2lo(h1a), y1[1] - h2hi(h1a));
    uint32_t l1b = pack_h2(y1[2] - h2lo(h1b), y1[3] - h2hi(h1b));
    uint32_t l2a = pack_h2(y2[0] - h2lo(h2a), y2[1] - h2hi(h2a));
    uint32_t l2b = pack_h2(y2[2] - h2lo(h2b), y2[3] - h2hi(h2b));
    uint16_t* qh = reinterpret_cast<uint16_t*>(g_qb_h);
    uint16_t* ql = reinterpret_cast<uint16_t*>(g_qb_l);
    *reinterpret_cast<uint2*>(qh + o + j)      = make_uint2(h1a, h1b);
    *reinterpret_cast<uint2*>(qh + o + 64 + j) = make_uint2(h2a, h2b);
    *reinterpret_cast<uint2*>(ql + o + j)      = make_uint2(l1a, l1b);
    *reinterpret_cast<uint2*>(ql + o + 64 + j) = make_uint2(l2a, l2b);
}

// ---------------- RoPE new K -> fp16 (hi only) scatter -----------------------
__global__ void rope_scatter_k_kernel()
{
    int idx = blockIdx.x * blockDim.x + threadIdx.x;
    if (idx >= NT_ * HKV_ * 16) return;
    int j   = (idx & 15) * 4;
    int th  = idx >> 4;
    int tok = th >> 3;
    int kvh = th & 7;
    int b   = tok >> 9;
    int s   = tok & 511;
    float pos = (float)(L_ + s);
    const float* src = g_ktmp + (size_t)th * D_;
    float4 a = *reinterpret_cast<const float4*>(src + j);
    float4 c4 = *reinterpret_cast<const float4*>(src + 64 + j);
    float x1[4] = {a.x, a.y, a.z, a.w};
    float x2[4] = {c4.x, c4.y, c4.z, c4.w};
    float y1[4], y2[4];
#pragma unroll
    for (int i = 0; i < 4; i++) {
        float ang = pos * exp2f((float)(j + i) * ROPE_C);
        float c, sn;
        sincosf(ang, &sn, &c);
        y1[i] = x1[i] * c - x2[i] * sn;
        y2[i] = x2[i] * c + x1[i] * sn;
    }
    size_t o = (((size_t)(b * T_ + L_ + s)) * HKV_ + kvh) * D_;
    uint16_t* kh = reinterpret_cast<uint16_t*>(g_kb_h);
    *reinterpret_cast<uint2*>(kh + o + j) =
        make_uint2(pack_h2(y1[0], y1[1]), pack_h2(y1[2], y1[3]));
    *reinterpret_cast<uint2*>(kh + o + 64 + j) =
        make_uint2(pack_h2(y2[0], y2[1]), pack_h2(y2[2], y2[3]));
}

// ---------------- new V -> fp16 (hi only) scatter ----------------------------
__global__ void scatter_v_kernel()
{
    int idx = blockIdx.x * blockDim.x + threadIdx.x;
    const int n = NT_ * HKV_ * D_ / 4;
    if (idx >= n) return;
    int e   = idx * 4;
    int tok = e >> 10;
    int r   = e & 1023;
    int b   = tok >> 9;
    int s   = tok & 511;
    float4 v = reinterpret_cast<const float4*>(g_vtmp)[idx];
    size_t o = (((size_t)(b * T_ + L_ + s)) * HKV_) * D_ + r;
    *reinterpret_cast<uint2*>(reinterpret_cast<uint16_t*>(g_vb_h) + o) =
        make_uint2(pack_h2(v.x, v.y), pack_h2(v.z, v.w));
}

// ---------------- cache -> fp16 (hi only) ------------------------------------
__global__ void copy_cache_kernel(const float4* __restrict__ kc,
                                  const float4* __restrict__ vc)
{
    int idx = blockIdx.x * blockDim.x + threadIdx.x;
    const int n = B_ * L_ * HKV_ * D_ / 4;
    if (idx >= n) return;
    const int perb4 = L_ * HKV_ * D_ / 4;
    int b = idx / perb4;
    size_t o = ((size_t)idx + (size_t)b * ((T_ - L_) * HKV_ * D_ / 4)) * 4;
    float4 k = kc[idx];
    float4 v = vc[idx];
    *reinterpret_cast<uint2*>(reinterpret_cast<uint16_t*>(g_kb_h) + o) =
        make_uint2(pack_h2(k.x, k.y), pack_h2(k.z, k.w));
    *reinterpret_cast<uint2*>(reinterpret_cast<uint16_t*>(g_vb_h) + o) =
        make_uint2(pack_h2(v.x, v.y), pack_h2(v.z, v.w));
}

// ============================================================================
// Tensor-core flash attention: QK 2-term (Qh+Ql vs Kh), PV 1-term (Ph*Vh).
// Stage = Kh 16K | Vh 16K = 32KB; double-buffered.
// ============================================================================
#define AT_STAGE 32768
#define AT_SMEM  (2 * AT_STAGE)
#define SC_LOG2E 0.12751884817f

__global__ __launch_bounds__(256, 1) void attn_mma()
{
    extern __shared__ char smem[];
    const uint32_t sb = smem_u32(smem);
    const int tid  = threadIdx.x;
    const int lane = tid & 31;
    const int w    = tid >> 5;
    const int g    = lane >> 2;
    const int t4   = lane & 3;
    const int qt   = blockIdx.x;
    const int hq   = blockIdx.y;
    const int b    = blockIdx.z;
    const int kvh  = hq >> 2;

    // stage Q (hi at 0, lo at 32K) then fragment to registers
    {
        const int qr  = tid >> 1;
        const int qcb = (tid & 1) * 8;
        const size_t qo = ((size_t)(b * S_ + qt * 128 + qr)) * (HQ_ * D_) + hq * D_;
#pragma unroll
        for (int i = 0; i < 8; i++) {
            int ch = qcb + i;
            uint32_t d = sb + qr * 256 + ((ch ^ (qr & 7)) * 16);
            CP_ASYNC16(d,         g_qb_h + qo + ch * 8);
            CP_ASYNC16(d + 32768, g_qb_l + qo + ch * 8);
        }
        CP_COMMIT();
        CP_WAIT0();
    }
    __syncthreads();

    uint32_t qh[8][4], ql[8][4];
    {
        const int tt  = lane >> 3;
        const int qrow = 16 * w + (tt & 1) * 8 + (lane & 7);
        const int chi  = tt >> 1;
#pragma unroll
        for (int kk = 0; kk < 8; kk++) {
            uint32_t a = sb + qrow * 256 + (((2 * kk + chi) ^ (qrow & 7)) * 16);
            LDSM4(qh[kk], a);
            LDSM4(ql[kk], a + 32768);
        }
    }
    __syncthreads();

    const int ntiles = 26 + 2 * qt;
    const int mask_from = 24 + 2 * qt;

    auto issueKV = [&](int stage, int kt) {
        const uint32_t s = sb + stage * AT_STAGE;
        const int trow = tid >> 2;
        const int cb   = (tid & 3) * 4;
        const size_t go = (((size_t)(b * T_ + kt * 64 + trow)) * HKV_ + kvh) * D_;
        const uint32_t rb = s + trow * 256;
#pragma unroll
        for (int i = 0; i < 4; i++) {
            int ch = cb + i;
            uint32_t d = rb + ((ch ^ (trow & 7)) * 16);
            CP_ASYNC16(d,         g_kb_h + go + ch * 8);
            CP_ASYNC16(d + 16384, g_vb_h + go + ch * 8);
        }
        CP_COMMIT();
    };

    issueKV(0, 0);
    issueKV(1, 1);

    float oacc[16][4];
#pragma unroll
    for (int j = 0; j < 16; j++) {
        oacc[j][0] = 0.f; oacc[j][1] = 0.f; oacc[j][2] = 0.f; oacc[j][3] = 0.f;
    }
    float m0 = -1e30f, m1 = -1e30f, l0 = 0.f, l1 = 0.f;

    const int tt   = lane >> 3;
    const int krb  = (tt >> 1) * 8 + (lane & 7);
    const int kch1 = tt & 1;
    const int vrb  = (tt & 1) * 8 + (lane & 7);
    const int vch1 = tt >> 1;

    for (int kt = 0; kt < ntiles; kt++) {
        if (kt + 1 < ntiles) { CP_WAIT1(); } else { CP_WAIT0(); }
        __syncthreads();

        const uint32_t s = sb + (kt & 1) * AT_STAGE;

        float sacc[8][4];
#pragma unroll
        for (int j = 0; j < 8; j++) {
            sacc[j][0] = 0.f; sacc[j][1] = 0.f; sacc[j][2] = 0.f; sacc[j][3] = 0.f;
        }
#pragma unroll
        for (int kk = 0; kk < 8; kk++) {
#pragma unroll
            for (int jp = 0; jp < 4; jp++) {
                const int trow = jp * 16 + krb;
                const uint32_t addr = s + trow * 256 +
                                      (((2 * kk + kch1) ^ (trow & 7)) * 16);
                uint32_t bh[4];
                LDSM4(bh, addr);
                MMA_F16(sacc[2*jp],   qh[kk], bh[0], bh[1]);
                MMA_F16(sacc[2*jp+1], qh[kk], bh[2], bh[3]);
                MMA_F16(sacc[2*jp],   ql[kk], bh[0], bh[1]);
                MMA_F16(sacc[2*jp+1], ql[kk], bh[2], bh[3]);
            }
        }

        if (kt >= mask_from) {
            const int colb = kt * 64 + 2 * t4;
            const int alw0 = L_ + qt * 128 + 16 * w + g;
            const int alw1 = alw0 + 8;
#pragma unroll
            for (int j = 0; j < 8; j++) {
                int c0 = colb + j * 8;
                if (c0 > alw0)     sacc[j][0] = -1e30f;
                if (c0 + 1 > alw0) sacc[j][1] = -1e30f;
                if (c0 > alw1)     sacc[j][2] = -1e30f;
                if (c0 + 1 > alw1) sacc[j][3] = -1e30f;
            }
        }

        float rm0 = -1e30f, rm1 = -1e30f;
#pragma unroll
        for (int j = 0; j < 8; j++) {
            rm0 = fmaxf(rm0, fmaxf(sacc[j][0], sacc[j][1]));
            rm1 = fmaxf(rm1, fmaxf(sacc[j][2], sacc[j][3]));
        }
        rm0 = fmaxf(rm0, __shfl_xor_sync(0xFFFFFFFFu, rm0, 1));
        rm0 = fmaxf(rm0, __shfl_xor_sync(0xFFFFFFFFu, rm0, 2));
        rm1 = fmaxf(rm1, __shfl_xor_sync(0xFFFFFFFFu, rm1, 1));
        rm1 = fmaxf(rm1, __shfl_xor_sync(0xFFFFFFFFu, rm1, 2));

        const float nm0 = fmaxf(m0, rm0), nm1 = fmaxf(m1, rm1);
        const float f0 = exp2f((m0 - nm0) * SC_LOG2E);
        const float f1 = exp2f((m1 - nm1) * SC_LOG2E);
        float rs0 = 0.f, rs1 = 0.f;
#pragma unroll
        for (int j = 0; j < 8; j++) {
            sacc[j][0] = exp2f((sacc[j][0] - nm0) * SC_LOG2E);
            sacc[j][1] = exp2f((sacc[j][1] - nm0) * SC_LOG2E);
            sacc[j][2] = exp2f((sacc[j][2] - nm1) * SC_LOG2E);
            sacc[j][3] = exp2f((sacc[j][3] - nm1) * SC_LOG2E);
            rs0 += sacc[j][0] + sacc[j][1];
            rs1 += sacc[j][2] + sacc[j][3];
        }
        rs0 += __shfl_xor_sync(0xFFFFFFFFu, rs0, 1);
        rs0 += __shfl_xor_sync(0xFFFFFFFFu, rs0, 2);
        rs1 += __shfl_xor_sync(0xFFFFFFFFu, rs1, 1);
        rs1 += __shfl_xor_sync(0xFFFFFFFFu, rs1, 2);
        l0 = l0 * f0 + rs0;
        l1 = l1 * f1 + rs1;
        m0 = nm0; m1 = nm1;

#pragma unroll
        for (int j = 0; j < 16; j++) {
            oacc[j][0] *= f0; oacc[j][1] *= f0;
            oacc[j][2] *= f1; oacc[j][3] *= f1;
        }

        // P fragments: hi only
        uint32_t ph[4][4];
#pragma unroll
        for (int kc = 0; kc < 4; kc++) {
            ph[kc][0] = pack_h2(sacc[2*kc][0],   sacc[2*kc][1]);
            ph[kc][1] = pack_h2(sacc[2*kc][2],   sacc[2*kc][3]);
            ph[kc][2] = pack_h2(sacc[2*kc+1][0], sacc[2*kc+1][1]);
            ph[kc][3] = pack_h2(sacc[2*kc+1][2], sacc[2*kc+1][3]);
        }

        // O += Ph @ Vh
        const uint32_t vbase = s + 16384;
#pragma unroll
        for (int jp2 = 0; jp2 < 8; jp2++) {
#pragma unroll
            for (int kc = 0; kc < 4; kc++) {
                const int trow = kc * 16 + vrb;
                const uint32_t addr = vbase + trow * 256 +
                                      (((jp2 * 2 + vch1) ^ (trow & 7)) * 16);
                uint32_t vh[4];
                LDSM4T(vh, addr);
                MMA_F16(oacc[2*jp2],   ph[kc], vh[0], vh[1]);
                MMA_F16(oacc[2*jp2+1], ph[kc], vh[2], vh[3]);
            }
        }

        __syncthreads();
        if (kt + 2 < ntiles) issueKV(kt & 1, kt + 2);
    }

    const float il0 = 1.0f / l0;
    const float il1 = 1.0f / l1;
    const size_t tok0 = (size_t)(b * S_ + qt * 128 + 16 * w + g);
    uint32_t* oh32 = reinterpret_cast<uint32_t*>(g_attb_h);
#pragma unroll
    for (int jn = 0; jn < 16; jn++) {
        float o0 = oacc[jn][0] * il0, o1 = oacc[jn][1] * il0;
        float o2 = oacc[jn][2] * il1, o3 = oacc[jn][3] * il1;
        const size_t a0 = (tok0 * (HQ_ * D_) + hq * D_ + jn * 8 + 2 * t4) >> 1;
        const size_t a1 = a0 + (8 * (HQ_ * D_) >> 1);
        oh32[a0] = pack_h2(o0, o1);
        oh32[a1] = pack_h2(o2, o3);
    }
}

// ---------------- launcher ---------------------------------------------------
extern "C" void kernel_launch(void* const* d_in, const int* in_sizes, int n_in,
                              void* d_out, int out_size)
{
    const float* hidden  = (const float*)d_in[0];
    const float* k_cache = (const float*)d_in[1];
    const float* v_cache = (const float*)d_in[2];
    const float* wq      = (const float*)d_in[3];
    const float* wk      = (const float*)d_in[4];
    const float* wv      = (const float*)d_in[5];
    const float* wo      = (const float*)d_in[6];
    float* out = (float*)d_out;

    float *q, *ktmp, *vtmp;
    cudaGetSymbolAddress((void**)&q,    g_q);
    cudaGetSymbolAddress((void**)&ktmp, g_ktmp);
    cudaGetSymbolAddress((void**)&vtmp, g_vtmp);

    __half *hid_h, *wqkv_h, *wo_h, *attb_h;
    cudaGetSymbolAddress((void**)&hid_h,  g_hid_h);
    cudaGetSymbolAddress((void**)&wqkv_h, g_wqkvT_h);
    cudaGetSymbolAddress((void**)&wo_h,   g_woT_h);
    cudaGetSymbolAddress((void**)&attb_h, g_attb_h);

    cudaFuncSetAttribute(gemm_h1,
                         cudaFuncAttributeMaxDynamicSharedMemorySize, GEMM_SMEM);
    cudaFuncSetAttribute(attn_mma,
                         cudaFuncAttributeMaxDynamicSharedMemorySize, AT_SMEM);

    // conversions
    conv_h<<<(NT_ * H_ / 4 + 255) / 256, 256>>>(
        (const float4*)hidden, (uint2*)hid_h, NT_ * H_ / 4);
    conv_hT<<<dim3(H_ / 32, H_ / 64), 256>>>(wq, wqkv_h, H_, H_);
    conv_hT<<<dim3((HKV_ * D_) / 32, H_ / 64), 256>>>(
        wk, wqkv_h + (size_t)H_ * H_, H_, HKV_ * D_);
    conv_hT<<<dim3((HKV_ * D_) / 32, H_ / 64), 256>>>(
        wv, wqkv_h + (size_t)(H_ + HKV_ * D_) * H_, H_, HKV_ * D_);
    conv_hT<<<dim3(H_ / 32, H_ / 64), 256>>>(wo, wo_h, H_, H_);

    // fused QKV projection
    gemm_h1<<<dim3(NQKV / 128, NT_ / 128), 256, GEMM_SMEM>>>(
        hid_h, wqkv_h,
        q, ktmp, vtmp, H_, H_ + HKV_ * D_, H_, HKV_ * D_, HKV_ * D_, H_);

    // rope + KV assembly
    rope_q_kernel<<<(NT_ * HQ_ * 16) / 256, 256>>>();
    rope_scatter_k_kernel<<<(NT_ * HKV_ * 16) / 256, 256>>>();
    scatter_v_kernel<<<(NT_ * HKV_ * D_ / 4) / 256, 256>>>();
    copy_cache_kernel<<<(B_ * L_ * HKV_ * D_ / 4) / 256, 256>>>(
        (const float4*)k_cache, (const float4*)v_cache);

    // attention
    attn_mma<<<dim3(S_ / 128, HQ_, B_), 256, AT_SMEM>>>();

    // output projection
    gemm_h1<<<dim3(H_ / 128, NT_ / 128), 256, GEMM_SMEM>>>(
        attb_h, wo_h,
        out, out, out, H_, H_, H_, H_, H_, H_);
}